// round 9
// baseline (speedup 1.0000x reference)
#include <cuda_runtime.h>
#include <cuda_bf16.h>
#include <cuda_fp16.h>
#include <cstdint>
#include <math.h>

#define M_TOT 8192
#define NQKV  6144
#define GK    2048

// ---------------- device scratch ----------------
__device__ __nv_bfloat16 g_qkvh[(size_t)M_TOT * NQKV];  // Q,K bf16 hi | V fp16 hi
__device__ __nv_bfloat16 g_qkvl[(size_t)M_TOT * NQKV];  // Q,K bf16 lo | V fp16 lo
__device__ __nv_bfloat16 g_xh[(size_t)M_TOT * GK];
__device__ __nv_bfloat16 g_xl[(size_t)M_TOT * GK];
__device__ __nv_bfloat16 g_wqh[(size_t)NQKV * GK];
__device__ __nv_bfloat16 g_wql[(size_t)NQKV * GK];
__device__ __nv_bfloat16 g_woh[(size_t)GK * GK];
__device__ __nv_bfloat16 g_wol[(size_t)GK * GK];
__device__ __nv_bfloat16 g_oh[(size_t)M_TOT * GK];
__device__ __nv_bfloat16 g_ol[(size_t)M_TOT * GK];

#define QSCALE (0.08838834764831845f * 1.4426950408889634f)

// ---------------- helpers ----------------
static __device__ __forceinline__ void split2u(float a, float b, uint32_t& h, uint32_t& l) {
    __nv_bfloat16 ha = __float2bfloat16(a);
    __nv_bfloat16 hb = __float2bfloat16(b);
    __nv_bfloat16 la = __float2bfloat16(a - __bfloat162float(ha));
    __nv_bfloat16 lb = __float2bfloat16(b - __bfloat162float(hb));
    h = (uint32_t)__bfloat16_as_ushort(ha) | ((uint32_t)__bfloat16_as_ushort(hb) << 16);
    l = (uint32_t)__bfloat16_as_ushort(la) | ((uint32_t)__bfloat16_as_ushort(lb) << 16);
}
static __device__ __forceinline__ void split2h(float a, float b, uint32_t& h, uint32_t& l) {
    __half ha = __float2half(a);
    __half hb = __float2half(b);
    __half la = __float2half(a - __half2float(ha));
    __half lb = __float2half(b - __half2float(hb));
    h = (uint32_t)__half_as_ushort(ha) | ((uint32_t)__half_as_ushort(hb) << 16);
    l = (uint32_t)__half_as_ushort(la) | ((uint32_t)__half_as_ushort(lb) << 16);
}

#define CPA16(dst, src) \
    asm volatile("cp.async.cg.shared.global [%0], [%1], 16;" :: "r"(dst), "l"(src))
#define CPA_COMMIT() asm volatile("cp.async.commit_group;")
#define CPA_WAIT2()  asm volatile("cp.async.wait_group 2;")
#define CPA_WAIT1()  asm volatile("cp.async.wait_group 1;")
#define CPA_WAIT0()  asm volatile("cp.async.wait_group 0;")

#define MMA16816(ac, a0, a1, a2, a3, b0, b1) \
    asm volatile("mma.sync.aligned.m16n8k16.row.col.f32.bf16.bf16.f32 " \
        "{%0,%1,%2,%3},{%4,%5,%6,%7},{%8,%9},{%0,%1,%2,%3};" \
        : "+f"((ac)[0]), "+f"((ac)[1]), "+f"((ac)[2]), "+f"((ac)[3]) \
        : "r"(a0), "r"(a1), "r"(a2), "r"(a3), "r"(b0), "r"(b1))

#define MMAH16816(ac, a0, a1, a2, a3, b0, b1) \
    asm volatile("mma.sync.aligned.m16n8k16.row.col.f32.f16.f16.f32 " \
        "{%0,%1,%2,%3},{%4,%5,%6,%7},{%8,%9},{%0,%1,%2,%3};" \
        : "+f"((ac)[0]), "+f"((ac)[1]), "+f"((ac)[2]), "+f"((ac)[3]) \
        : "r"(a0), "r"(a1), "r"(a2), "r"(a3), "r"(b0), "r"(b1))

#define LDSM4(r0, r1, r2, r3, addr) \
    asm volatile("ldmatrix.sync.aligned.m8n8.x4.shared.b16 {%0,%1,%2,%3}, [%4];" \
        : "=r"(r0), "=r"(r1), "=r"(r2), "=r"(r3) : "r"(addr))
#define LDSM4T(r0, r1, r2, r3, addr) \
    asm volatile("ldmatrix.sync.aligned.m8n8.x4.trans.shared.b16 {%0,%1,%2,%3}, [%4];" \
        : "=r"(r0), "=r"(r1), "=r"(r2), "=r"(r3) : "r"(addr))

// pack two fp32 (x1 -> hi, x0 -> lo) then exp2 both halves in one MUFU op
#define EXP2PAIR(d, x1, x0) do {                                     \
    uint32_t _t;                                                     \
    asm("cvt.rn.f16x2.f32 %0, %1, %2;" : "=r"(_t) : "f"(x1), "f"(x0)); \
    asm("ex2.approx.f16x2 %0, %1;" : "=r"(d) : "r"(_t));             \
} while (0)

// ---------------- conversion kernels ----------------
__global__ void ksplit(const float* __restrict__ in, __nv_bfloat16* __restrict__ hi,
                       __nv_bfloat16* __restrict__ lo, int n4)
{
    int i = blockIdx.x * blockDim.x + threadIdx.x;
    if (i >= n4) return;
    float4 v = ((const float4*)in)[i];
    uint2 h, l;
    split2u(v.x, v.y, h.x, l.x);
    split2u(v.z, v.w, h.y, l.y);
    ((uint2*)hi)[i] = h;
    ((uint2*)lo)[i] = l;
}

__global__ void ksplitT(const float* __restrict__ in, __nv_bfloat16* __restrict__ hiT,
                        __nv_bfloat16* __restrict__ loT, int K, int N)
{
    __shared__ float t[32][33];
    int n0 = blockIdx.x * 32, k0 = blockIdx.y * 32;
    int tx = threadIdx.x, ty = threadIdx.y;
    #pragma unroll
    for (int j = 0; j < 32; j += 8)
        t[ty + j][tx] = in[(size_t)(k0 + ty + j) * N + n0 + tx];
    __syncthreads();
    #pragma unroll
    for (int j = 0; j < 32; j += 8) {
        float v = t[tx][ty + j];
        __nv_bfloat16 h = __float2bfloat16(v);
        __nv_bfloat16 l = __float2bfloat16(v - __bfloat162float(h));
        size_t oi = (size_t)(n0 + ty + j) * K + k0 + tx;
        hiT[oi] = h;
        loT[oi] = l;
    }
}

// ---------------- mma.sync bf16x3 GEMM ----------------
// Block 256x128x32, 8 warps of 64x64, 3-stage cp.async pipeline.
#define SROW  80
#define A_T   (256 * SROW)          // 20480
#define B_T   (128 * SROW)          // 10240
#define STG   (2 * A_T + 2 * B_T)   // 61440: Ah | Al | Bh | Bl
#define GSMEM (3 * STG)             // 184320

__global__ __launch_bounds__(256)
void gemm_mma_bf16x3(const __nv_bfloat16* __restrict__ Ah,
                     const __nv_bfloat16* __restrict__ Al,
                     const __nv_bfloat16* __restrict__ Bh,
                     const __nv_bfloat16* __restrict__ Bl,
                     float* __restrict__ C,
                     __nv_bfloat16* __restrict__ Cbh,
                     __nv_bfloat16* __restrict__ Cbl,
                     int ldc, int mode)
{
    extern __shared__ __align__(16) char smem[];
    const uint32_t sbase = (uint32_t)__cvta_generic_to_shared(smem);
    const int tid  = threadIdx.x;
    const int warp = tid >> 5, lane = tid & 31;
    const int m0 = blockIdx.y * 256, n0 = blockIdx.x * 128;
    const int wm = (warp & 3) * 64, wn = (warp >> 2) * 64;

    auto issue = [&](int st, int k0) {
        uint32_t dbase = sbase + st * STG;
        #pragma unroll
        for (int t = 0; t < 12; t++) {
            int i = tid + t * 256;
            const __nv_bfloat16* g;
            uint32_t d;
            if (i < 1024) {
                int r = i >> 2, c = i & 3;
                g = Ah + (size_t)(m0 + r) * GK + k0 + c * 8;
                d = dbase + r * SROW + c * 16;
            } else if (i < 2048) {
                int j = i - 1024, r = j >> 2, c = j & 3;
                g = Al + (size_t)(m0 + r) * GK + k0 + c * 8;
                d = dbase + A_T + r * SROW + c * 16;
            } else if (i < 2560) {
                int j = i - 2048, r = j >> 2, c = j & 3;
                g = Bh + (size_t)(n0 + r) * GK + k0 + c * 8;
                d = dbase + 2 * A_T + r * SROW + c * 16;
            } else {
                int j = i - 2560, r = j >> 2, c = j & 3;
                g = Bl + (size_t)(n0 + r) * GK + k0 + c * 8;
                d = dbase + 2 * A_T + B_T + r * SROW + c * 16;
            }
            CPA16(d, (const void*)g);
        }
        CPA_COMMIT();
    };

    float acc[4][8][4];
    #pragma unroll
    for (int mi = 0; mi < 4; mi++)
        #pragma unroll
        for (int n8 = 0; n8 < 8; n8++)
            #pragma unroll
            for (int q = 0; q < 4; q++) acc[mi][n8][q] = 0.0f;

    issue(0, 0);
    issue(1, 32);

    const int lr = lane >> 2;
    const int arow = lane & 15, ahalf = (lane >> 4) * 16;
    const int brow = (lane & 7) + ((lane >> 4) << 3);
    const int bhalf = ((lane >> 3) & 1) * 16;

    for (int ch = 0; ch < 64; ch++) {
        int buf = ch % 3;
        if (ch + 2 < 64) { issue((ch + 2) % 3, (ch + 2) * 32); CPA_WAIT2(); }
        else if (ch + 1 < 64) { CPA_WAIT1(); }
        else { CPA_WAIT0(); }
        __syncthreads();

        const uint32_t sb  = sbase + buf * STG;
        const uint32_t sAh = sb, sAl = sb + A_T;
        const uint32_t sBh = sb + 2 * A_T, sBl = sb + 2 * A_T + B_T;

        #pragma unroll
        for (int k16 = 0; k16 < 2; k16++) {
            const int kb2 = k16 * 32;
            uint32_t bh[8][2], bl[8][2];
            #pragma unroll
            for (int np = 0; np < 4; np++) {
                uint32_t ba = (wn + np * 16 + brow) * SROW + kb2 + bhalf;
                LDSM4(bh[2 * np][0], bh[2 * np][1], bh[2 * np + 1][0], bh[2 * np + 1][1],
                      sBh + ba);
                LDSM4(bl[2 * np][0], bl[2 * np][1], bl[2 * np + 1][0], bl[2 * np + 1][1],
                      sBl + ba);
            }
            #pragma unroll
            for (int mi = 0; mi < 4; mi++) {
                uint32_t aa = (wm + mi * 16 + arow) * SROW + kb2 + ahalf;
                uint32_t ah0, ah1, ah2, ah3, al0, al1, al2, al3;
                LDSM4(ah0, ah1, ah2, ah3, sAh + aa);
                LDSM4(al0, al1, al2, al3, sAl + aa);
                #pragma unroll
                for (int n8 = 0; n8 < 8; n8++) {
                    MMA16816(acc[mi][n8], ah0, ah1, ah2, ah3, bh[n8][0], bh[n8][1]);
                    MMA16816(acc[mi][n8], ah0, ah1, ah2, ah3, bl[n8][0], bl[n8][1]);
                    MMA16816(acc[mi][n8], al0, al1, al2, al3, bh[n8][0], bh[n8][1]);
                }
            }
        }
        __syncthreads();
    }

    #pragma unroll
    for (int mi = 0; mi < 4; mi++) {
        int row = m0 + wm + mi * 16 + lr;
        #pragma unroll
        for (int n8 = 0; n8 < 8; n8++) {
            int col = n0 + wn + n8 * 8 + (lane & 3) * 2;
            if (mode == 0) {
                float* p0 = C + (size_t)row * ldc + col;
                float* p1 = C + (size_t)(row + 8) * ldc + col;
                p0[0] = acc[mi][n8][0]; p0[1] = acc[mi][n8][1];
                p1[0] = acc[mi][n8][2]; p1[1] = acc[mi][n8][3];
            } else {
                uint32_t h0, l0, h1, l1;
                if (col >= 4096) {
                    split2h(acc[mi][n8][0], acc[mi][n8][1], h0, l0);
                    split2h(acc[mi][n8][2], acc[mi][n8][3], h1, l1);
                } else {
                    float sc = (col < 2048) ? QSCALE : 1.0f;
                    split2u(acc[mi][n8][0] * sc, acc[mi][n8][1] * sc, h0, l0);
                    split2u(acc[mi][n8][2] * sc, acc[mi][n8][3] * sc, h1, l1);
                }
                *(uint32_t*)(Cbh + (size_t)row * ldc + col) = h0;
                *(uint32_t*)(Cbl + (size_t)row * ldc + col) = l0;
                *(uint32_t*)(Cbh + (size_t)(row + 8) * ldc + col) = h1;
                *(uint32_t*)(Cbl + (size_t)(row + 8) * ldc + col) = l1;
            }
        }
    }
}

// ---------------- flash attention (mma.sync) ----------------
// Q,K bf16 hi/lo (3 S-passes, Q frags preloaded to regs);
// softmax via ex2.approx.f16x2 (P emerges packed fp16); V fp16 hi/lo (2 PV passes).
#define SRA   272
#define TEN_B (128 * SRA)
#define FSMEM (6 * TEN_B)

__global__ __launch_bounds__(256, 1)
void flash_mma(const __nv_bfloat16* __restrict__ qh, const __nv_bfloat16* __restrict__ ql,
               __nv_bfloat16* __restrict__ oh, __nv_bfloat16* __restrict__ ol)
{
    extern __shared__ __align__(16) char sm[];
    const uint32_t S0 = (uint32_t)__cvta_generic_to_shared(sm);
    const uint32_t oQh = 0, oQl = TEN_B, oKh = 2 * TEN_B, oKl = 3 * TEN_B,
                   oVh = 4 * TEN_B, oVl = 5 * TEN_B;

    const int tid = threadIdx.x, warp = tid >> 5, lane = tid & 31;
    const int lr = lane >> 2, lc = lane & 3;
    const int qt = blockIdx.x, h = blockIdx.y, b = blockIdx.z;
    const size_t rowbase = (size_t)(b * 2048 + h * 128) * 6144;

    const int arow = lane & 15, ahalf = (lane >> 4) * 16;
    const int brow = (lane & 7) + ((lane >> 4) << 3);
    const int bhalf = ((lane >> 3) & 1) * 16;

    auto issue_kv = [&](int t64, int buf) {
        #pragma unroll
        for (int t = 0; t < 16; t++) {
            int i = tid + t * 256;
            int sub = i >> 10;
            int j = i & 1023;
            int r = j >> 4, c = j & 15;
            int koff = (sub >> 1) ? 4096 : 2048;
            const __nv_bfloat16* base = (sub & 1) ? ql : qh;
            const __nv_bfloat16* src = base + rowbase
                + (size_t)(t64 * 4 + (r >> 4)) * 6144 + ((r & 15) << 7) + koff + c * 8;
            uint32_t off = (sub & 1) ? ((sub >> 1) ? oVl : oKl) : ((sub >> 1) ? oVh : oKh);
            CPA16(S0 + off + (buf * 64 + r) * SRA + c * 16, src);
        }
        CPA_COMMIT();
    };

    #pragma unroll
    for (int t = 0; t < 16; t++) {
        int i = tid + t * 256;
        int sub = i >> 11;
        int j = i & 2047;
        int r = j >> 4, c = j & 15;
        const __nv_bfloat16* src = (sub ? ql : qh) + rowbase
            + (size_t)(qt * 8 + (r >> 4)) * 6144 + ((r & 15) << 7) + c * 8;
        CPA16(S0 + (sub ? oQl : oQh) + r * SRA + c * 16, src);
    }
    CPA_COMMIT();

    const int nt = 2 * qt + 2;
    issue_kv(0, 0);

    float accO[16][4];
    #pragma unroll
    for (int ni = 0; ni < 16; ni++)
        #pragma unroll
        for (int q = 0; q < 4; q++) accO[ni][q] = 0.0f;
    float mrow[2] = {-1e30f, -1e30f}, lrow[2] = {0.0f, 0.0f};
    uint32_t qf[8][8];   // preloaded Q fragments: [dk][hi0..3, lo0..3]

    for (int t64 = 0; t64 < nt; t64++) {
        int buf = t64 & 1;
        if (t64 + 1 < nt) { issue_kv(t64 + 1, buf ^ 1); CPA_WAIT1(); }
        else              { CPA_WAIT0(); }
        __syncthreads();

        if (t64 == 0) {
            #pragma unroll
            for (int dk = 0; dk < 8; dk++) {
                uint32_t qa = S0 + oQh + (warp * 16 + arow) * SRA + dk * 32 + ahalf;
                LDSM4(qf[dk][0], qf[dk][1], qf[dk][2], qf[dk][3], qa);
                LDSM4(qf[dk][4], qf[dk][5], qf[dk][6], qf[dk][7], qa + TEN_B);
            }
        }

        const uint32_t kbB = buf * 64 * SRA;

        // ---- S = Q @ K^T (bf16 hi/lo, 3 passes) ----
        float sacc[8][4];
        #pragma unroll
        for (int ni = 0; ni < 8; ni++)
            #pragma unroll
            for (int q = 0; q < 4; q++) sacc[ni][q] = 0.0f;

        #pragma unroll
        for (int dk = 0; dk < 8; dk++) {
            #pragma unroll
            for (int np = 0; np < 4; np++) {
                uint32_t ka = S0 + oKh + kbB + (np * 16 + brow) * SRA + dk * 32 + bhalf;
                uint32_t bh0, bh1, bh2, bh3, bl0, bl1, bl2, bl3;
                LDSM4(bh0, bh1, bh2, bh3, ka);
                LDSM4(bl0, bl1, bl2, bl3, ka + TEN_B);
                MMA16816(sacc[2 * np], qf[dk][0], qf[dk][1], qf[dk][2], qf[dk][3], bh0, bh1);
                MMA16816(sacc[2 * np], qf[dk][0], qf[dk][1], qf[dk][2], qf[dk][3], bl0, bl1);
                MMA16816(sacc[2 * np], qf[dk][4], qf[dk][5], qf[dk][6], qf[dk][7], bh0, bh1);
                MMA16816(sacc[2 * np + 1], qf[dk][0], qf[dk][1], qf[dk][2], qf[dk][3], bh2, bh3);
                MMA16816(sacc[2 * np + 1], qf[dk][0], qf[dk][1], qf[dk][2], qf[dk][3], bl2, bl3);
                MMA16816(sacc[2 * np + 1], qf[dk][4], qf[dk][5], qf[dk][6], qf[dk][7], bh2, bh3);
            }
        }

        // ---- causal mask ----
        if (t64 >= 2 * qt) {
            #pragma unroll
            for (int ni = 0; ni < 8; ni++)
                #pragma unroll
                for (int q = 0; q < 4; q++) {
                    int col_g = t64 * 64 + ni * 8 + lc * 2 + (q & 1);
                    int row_g = qt * 128 + warp * 16 + lr + (q >> 1) * 8;
                    if (col_g > row_g) sacc[ni][q] = -1e30f;
                }
        }

        // ---- online softmax; P computed packed-fp16 via ex2.approx.f16x2 ----
        float corr[2];
        uint32_t ph[8][2];
        #pragma unroll
        for (int hf = 0; hf < 2; hf++) {
            float rm = -1e30f;
            #pragma unroll
            for (int ni = 0; ni < 8; ni++)
                rm = fmaxf(rm, fmaxf(sacc[ni][hf * 2], sacc[ni][hf * 2 + 1]));
            rm = fmaxf(rm, __shfl_xor_sync(0xffffffffu, rm, 1));
            rm = fmaxf(rm, __shfl_xor_sync(0xffffffffu, rm, 2));
            float mnew = fmaxf(mrow[hf], rm);
            corr[hf] = exp2f(mrow[hf] - mnew);
            mrow[hf] = mnew;
            float ls = 0.0f;
            #pragma unroll
            for (int ni = 0; ni < 8; ni++) {
                uint32_t p;
                EXP2PAIR(p, sacc[ni][hf * 2 + 1] - mnew, sacc[ni][hf * 2] - mnew);
                ph[ni][hf] = p;
                float2 f = __half22float2(*reinterpret_cast<__half2*>(&p));
                ls += f.x + f.y;
            }
            lrow[hf] = lrow[hf] * corr[hf] + ls;
        }
        #pragma unroll
        for (int ni = 0; ni < 16; ni++)
            #pragma unroll
            for (int q = 0; q < 4; q++) accO[ni][q] *= corr[q >> 1];

        // ---- O += P @ V (P fp16 packed from exp, V fp16 hi/lo -> 2 passes) ----
        #pragma unroll
        for (int j = 0; j < 4; j++) {
            uint32_t pa0 = ph[2 * j][0], pa1 = ph[2 * j][1];
            uint32_t pa2 = ph[2 * j + 1][0], pa3 = ph[2 * j + 1][1];
            #pragma unroll
            for (int n2 = 0; n2 < 8; n2++) {
                uint32_t va = S0 + oVh + kbB + (j * 16 + (lane & 15)) * SRA
                            + n2 * 32 + (lane >> 4) * 16;
                uint32_t vh0, vh1, vh2, vh3, vl0, vl1, vl2, vl3;
                LDSM4T(vh0, vh1, vh2, vh3, va);
                LDSM4T(vl0, vl1, vl2, vl3, va + TEN_B);
                MMAH16816(accO[2 * n2], pa0, pa1, pa2, pa3, vh0, vh1);
                MMAH16816(accO[2 * n2], pa0, pa1, pa2, pa3, vl0, vl1);
                MMAH16816(accO[2 * n2 + 1], pa0, pa1, pa2, pa3, vh2, vh3);
                MMAH16816(accO[2 * n2 + 1], pa0, pa1, pa2, pa3, vl2, vl3);
            }
        }
        __syncthreads();
    }

    // ---- normalize + write O (bf16 hi/lo, head-contiguous) ----
    float inv[2];
    #pragma unroll
    for (int hf = 0; hf < 2; hf++) {
        float ls = lrow[hf];
        ls += __shfl_xor_sync(0xffffffffu, ls, 1);
        ls += __shfl_xor_sync(0xffffffffu, ls, 2);
        inv[hf] = 1.0f / ls;
    }
    #pragma unroll
    for (int hf = 0; hf < 2; hf++) {
        int srow = qt * 128 + warp * 16 + lr + hf * 8;
        size_t base = ((size_t)(b * 16 + h) * 2048 + srow) << 7;
        #pragma unroll
        for (int ni = 0; ni < 16; ni++) {
            int d = ni * 8 + lc * 2;
            uint32_t hh, ll;
            split2u(accO[ni][hf * 2] * inv[hf], accO[ni][hf * 2 + 1] * inv[hf], hh, ll);
            *(uint32_t*)(oh + base + d) = hh;
            *(uint32_t*)(ol + base + d) = ll;
        }
    }
}

// ---------------------------------------------------------------------------
extern "C" void kernel_launch(void* const* d_in, const int* in_sizes, int n_in,
                              void* d_out, int out_size)
{
    (void)in_sizes; (void)n_in; (void)out_size;
    const float* x    = (const float*)d_in[0];
    const float* wqkv = (const float*)d_in[1];
    const float* wout = (const float*)d_in[2];
    float* out = (float*)d_out;

    __nv_bfloat16 *qkvh, *qkvl, *xh, *xl, *wqh, *wql, *woh, *wol, *oh, *ol;
    cudaGetSymbolAddress((void**)&qkvh, g_qkvh); cudaGetSymbolAddress((void**)&qkvl, g_qkvl);
    cudaGetSymbolAddress((void**)&xh, g_xh);     cudaGetSymbolAddress((void**)&xl, g_xl);
    cudaGetSymbolAddress((void**)&wqh, g_wqh);   cudaGetSymbolAddress((void**)&wql, g_wql);
    cudaGetSymbolAddress((void**)&woh, g_woh);   cudaGetSymbolAddress((void**)&wol, g_wol);
    cudaGetSymbolAddress((void**)&oh, g_oh);     cudaGetSymbolAddress((void**)&ol, g_ol);

    cudaFuncSetAttribute(gemm_mma_bf16x3,
                         cudaFuncAttributeMaxDynamicSharedMemorySize, GSMEM);
    cudaFuncSetAttribute(flash_mma,
                         cudaFuncAttributeMaxDynamicSharedMemorySize, FSMEM);

    ksplit<<<(M_TOT * GK / 4 + 255) / 256, 256>>>(x, xh, xl, M_TOT * GK / 4);
    ksplitT<<<dim3(NQKV / 32, GK / 32), dim3(32, 8)>>>(wqkv, wqh, wql, GK, NQKV);
    ksplitT<<<dim3(GK / 32, GK / 32), dim3(32, 8)>>>(wout, woh, wol, GK, GK);

    gemm_mma_bf16x3<<<dim3(NQKV / 128, M_TOT / 256), 256, GSMEM>>>(
        xh, xl, wqh, wql, nullptr, qkvh, qkvl, NQKV, 1);

    flash_mma<<<dim3(16, 16, 4), 256, FSMEM>>>(qkvh, qkvl, oh, ol);

    gemm_mma_bf16x3<<<dim3(GK / 128, M_TOT / 256), 256, GSMEM>>>(
        oh, ol, woh, wol, out, nullptr, nullptr, GK, 0);
}

// round 10
// speedup vs baseline: 1.1382x; 1.1382x over previous
#include <cuda_runtime.h>
#include <cuda_bf16.h>
#include <cuda_fp16.h>
#include <cstdint>
#include <math.h>

#define M_TOT 8192
#define NQKV  6144
#define GK    2048

// ---------------- device scratch ----------------
__device__ __nv_bfloat16 g_qkvh[(size_t)M_TOT * NQKV];  // Q,K bf16 hi | V fp16 hi
__device__ __nv_bfloat16 g_qkvl[(size_t)M_TOT * NQKV];  // Q,K bf16 lo | V fp16 lo
__device__ __nv_bfloat16 g_xh[(size_t)M_TOT * GK];
__device__ __nv_bfloat16 g_xl[(size_t)M_TOT * GK];
__device__ __nv_bfloat16 g_wqh[(size_t)NQKV * GK];
__device__ __nv_bfloat16 g_wql[(size_t)NQKV * GK];
__device__ __nv_bfloat16 g_woh[(size_t)GK * GK];
__device__ __nv_bfloat16 g_wol[(size_t)GK * GK];
__device__ __nv_bfloat16 g_oh[(size_t)M_TOT * GK];
__device__ __nv_bfloat16 g_ol[(size_t)M_TOT * GK];

#define QSCALE (0.08838834764831845f * 1.4426950408889634f)

// ---------------- helpers ----------------
static __device__ __forceinline__ void split2u(float a, float b, uint32_t& h, uint32_t& l) {
    __nv_bfloat16 ha = __float2bfloat16(a);
    __nv_bfloat16 hb = __float2bfloat16(b);
    __nv_bfloat16 la = __float2bfloat16(a - __bfloat162float(ha));
    __nv_bfloat16 lb = __float2bfloat16(b - __bfloat162float(hb));
    h = (uint32_t)__bfloat16_as_ushort(ha) | ((uint32_t)__bfloat16_as_ushort(hb) << 16);
    l = (uint32_t)__bfloat16_as_ushort(la) | ((uint32_t)__bfloat16_as_ushort(lb) << 16);
}
static __device__ __forceinline__ void split2h(float a, float b, uint32_t& h, uint32_t& l) {
    __half ha = __float2half(a);
    __half hb = __float2half(b);
    __half la = __float2half(a - __half2float(ha));
    __half lb = __float2half(b - __half2float(hb));
    h = (uint32_t)__half_as_ushort(ha) | ((uint32_t)__half_as_ushort(hb) << 16);
    l = (uint32_t)__half_as_ushort(la) | ((uint32_t)__half_as_ushort(lb) << 16);
}

#define CPA16(dst, src) \
    asm volatile("cp.async.cg.shared.global [%0], [%1], 16;" :: "r"(dst), "l"(src))
#define CPA_COMMIT() asm volatile("cp.async.commit_group;")
#define CPA_WAIT1()  asm volatile("cp.async.wait_group 1;")
#define CPA_WAIT0()  asm volatile("cp.async.wait_group 0;")

#define MMA16816(ac, a0, a1, a2, a3, b0, b1) \
    asm volatile("mma.sync.aligned.m16n8k16.row.col.f32.bf16.bf16.f32 " \
        "{%0,%1,%2,%3},{%4,%5,%6,%7},{%8,%9},{%0,%1,%2,%3};" \
        : "+f"((ac)[0]), "+f"((ac)[1]), "+f"((ac)[2]), "+f"((ac)[3]) \
        : "r"(a0), "r"(a1), "r"(a2), "r"(a3), "r"(b0), "r"(b1))

#define MMAH16816(ac, a0, a1, a2, a3, b0, b1) \
    asm volatile("mma.sync.aligned.m16n8k16.row.col.f32.f16.f16.f32 " \
        "{%0,%1,%2,%3},{%4,%5,%6,%7},{%8,%9},{%0,%1,%2,%3};" \
        : "+f"((ac)[0]), "+f"((ac)[1]), "+f"((ac)[2]), "+f"((ac)[3]) \
        : "r"(a0), "r"(a1), "r"(a2), "r"(a3), "r"(b0), "r"(b1))

#define LDSM4(r0, r1, r2, r3, addr) \
    asm volatile("ldmatrix.sync.aligned.m8n8.x4.shared.b16 {%0,%1,%2,%3}, [%4];" \
        : "=r"(r0), "=r"(r1), "=r"(r2), "=r"(r3) : "r"(addr))
#define LDSM4T(r0, r1, r2, r3, addr) \
    asm volatile("ldmatrix.sync.aligned.m8n8.x4.trans.shared.b16 {%0,%1,%2,%3}, [%4];" \
        : "=r"(r0), "=r"(r1), "=r"(r2), "=r"(r3) : "r"(addr))

// pack two fp32 (x1 -> hi, x0 -> lo) then exp2 both halves in one MUFU op
#define EXP2PAIR(d, x1, x0) do {                                     \
    uint32_t _t;                                                     \
    asm("cvt.rn.f16x2.f32 %0, %1, %2;" : "=r"(_t) : "f"(x1), "f"(x0)); \
    asm("ex2.approx.f16x2 %0, %1;" : "=r"(d) : "r"(_t));             \
} while (0)

// ---------------- conversion kernels ----------------
__global__ void ksplit(const float* __restrict__ in, __nv_bfloat16* __restrict__ hi,
                       __nv_bfloat16* __restrict__ lo, int n4)
{
    int i = blockIdx.x * blockDim.x + threadIdx.x;
    if (i >= n4) return;
    float4 v = ((const float4*)in)[i];
    uint2 h, l;
    split2u(v.x, v.y, h.x, l.x);
    split2u(v.z, v.w, h.y, l.y);
    ((uint2*)hi)[i] = h;
    ((uint2*)lo)[i] = l;
}

__global__ void ksplitT(const float* __restrict__ in, __nv_bfloat16* __restrict__ hiT,
                        __nv_bfloat16* __restrict__ loT, int K, int N)
{
    __shared__ float t[32][33];
    int n0 = blockIdx.x * 32, k0 = blockIdx.y * 32;
    int tx = threadIdx.x, ty = threadIdx.y;
    #pragma unroll
    for (int j = 0; j < 32; j += 8)
        t[ty + j][tx] = in[(size_t)(k0 + ty + j) * N + n0 + tx];
    __syncthreads();
    #pragma unroll
    for (int j = 0; j < 32; j += 8) {
        float v = t[tx][ty + j];
        __nv_bfloat16 h = __float2bfloat16(v);
        __nv_bfloat16 l = __float2bfloat16(v - __bfloat162float(h));
        size_t oi = (size_t)(n0 + ty + j) * K + k0 + tx;
        hiT[oi] = h;
        loT[oi] = l;
    }
}

// ---------------- mma.sync bf16x3 GEMM (R7 config: 128x128x32, 2-stage) ----------------
#define SROW    80
#define TILE_B  (128 * SROW)
#define STAGE_B (4 * TILE_B)
#define GSMEM   (2 * STAGE_B)

__global__ __launch_bounds__(256)
void gemm_mma_bf16x3(const __nv_bfloat16* __restrict__ Ah,
                     const __nv_bfloat16* __restrict__ Al,
                     const __nv_bfloat16* __restrict__ Bh,
                     const __nv_bfloat16* __restrict__ Bl,
                     float* __restrict__ C,
                     __nv_bfloat16* __restrict__ Cbh,
                     __nv_bfloat16* __restrict__ Cbl,
                     int ldc, int mode)
{
    extern __shared__ __align__(16) char smem[];
    const uint32_t sbase = (uint32_t)__cvta_generic_to_shared(smem);
    const int tid  = threadIdx.x;
    const int warp = tid >> 5, lane = tid & 31;
    const int m0 = blockIdx.y * 128, n0 = blockIdx.x * 128;
    const int wm = (warp & 1) * 64, wn = (warp >> 1) * 32;

    auto issue = [&](int st, int k0) {
        uint32_t dbase = sbase + st * STAGE_B;
        #pragma unroll
        for (int t = 0; t < 8; t++) {
            int i = tid + t * 256;
            int sub = i >> 9;
            int j = i & 511;
            int r = j >> 2, c = j & 3;
            const __nv_bfloat16* g =
                (sub == 0) ? Ah + (size_t)(m0 + r) * GK + k0 + c * 8 :
                (sub == 1) ? Al + (size_t)(m0 + r) * GK + k0 + c * 8 :
                (sub == 2) ? Bh + (size_t)(n0 + r) * GK + k0 + c * 8 :
                             Bl + (size_t)(n0 + r) * GK + k0 + c * 8;
            uint32_t d = dbase + sub * TILE_B + r * SROW + c * 16;
            CPA16(d, (const void*)g);
        }
        CPA_COMMIT();
    };

    float acc[4][4][4];
    #pragma unroll
    for (int mi = 0; mi < 4; mi++)
        #pragma unroll
        for (int ni = 0; ni < 4; ni++)
            #pragma unroll
            for (int q = 0; q < 4; q++) acc[mi][ni][q] = 0.0f;

    issue(0, 0);

    const int lr = lane >> 2;
    const int arow = lane & 15, ahalf = (lane >> 4) * 16;
    const int brow = (lane & 7) + ((lane >> 4) << 3);
    const int bhalf = ((lane >> 3) & 1) * 16;

    for (int ch = 0; ch < 64; ch++) {
        int buf = ch & 1;
        if (ch < 63) { issue(buf ^ 1, (ch + 1) * 32); CPA_WAIT1(); }
        else         { CPA_WAIT0(); }
        __syncthreads();

        const uint32_t sb  = sbase + buf * STAGE_B;
        const uint32_t sAh = sb, sAl = sb + TILE_B;
        const uint32_t sBh = sb + 2 * TILE_B, sBl = sb + 3 * TILE_B;

        #pragma unroll
        for (int k16 = 0; k16 < 2; k16++) {
            const int kb2 = k16 * 32;
            uint32_t bh[4][2], bl[4][2];
            #pragma unroll
            for (int np = 0; np < 2; np++) {
                uint32_t ba = (wn + np * 16 + brow) * SROW + kb2 + bhalf;
                LDSM4(bh[2 * np][0], bh[2 * np][1], bh[2 * np + 1][0], bh[2 * np + 1][1],
                      sBh + ba);
                LDSM4(bl[2 * np][0], bl[2 * np][1], bl[2 * np + 1][0], bl[2 * np + 1][1],
                      sBl + ba);
            }
            #pragma unroll
            for (int mi = 0; mi < 4; mi++) {
                uint32_t aa = (wm + mi * 16 + arow) * SROW + kb2 + ahalf;
                uint32_t ah0, ah1, ah2, ah3, al0, al1, al2, al3;
                LDSM4(ah0, ah1, ah2, ah3, sAh + aa);
                LDSM4(al0, al1, al2, al3, sAl + aa);
                #pragma unroll
                for (int ni = 0; ni < 4; ni++) {
                    MMA16816(acc[mi][ni], ah0, ah1, ah2, ah3, bh[ni][0], bh[ni][1]);
                    MMA16816(acc[mi][ni], ah0, ah1, ah2, ah3, bl[ni][0], bl[ni][1]);
                    MMA16816(acc[mi][ni], al0, al1, al2, al3, bh[ni][0], bh[ni][1]);
                }
            }
        }
        __syncthreads();
    }

    #pragma unroll
    for (int mi = 0; mi < 4; mi++) {
        int row = m0 + wm + mi * 16 + lr;
        #pragma unroll
        for (int ni = 0; ni < 4; ni++) {
            int col = n0 + wn + ni * 8 + (lane & 3) * 2;
            if (mode == 0) {
                float* p0 = C + (size_t)row * ldc + col;
                float* p1 = C + (size_t)(row + 8) * ldc + col;
                p0[0] = acc[mi][ni][0]; p0[1] = acc[mi][ni][1];
                p1[0] = acc[mi][ni][2]; p1[1] = acc[mi][ni][3];
            } else {
                uint32_t h0, l0, h1, l1;
                if (col >= 4096) {
                    split2h(acc[mi][ni][0], acc[mi][ni][1], h0, l0);
                    split2h(acc[mi][ni][2], acc[mi][ni][3], h1, l1);
                } else {
                    float sc = (col < 2048) ? QSCALE : 1.0f;
                    split2u(acc[mi][ni][0] * sc, acc[mi][ni][1] * sc, h0, l0);
                    split2u(acc[mi][ni][2] * sc, acc[mi][ni][3] * sc, h1, l1);
                }
                *(uint32_t*)(Cbh + (size_t)row * ldc + col) = h0;
                *(uint32_t*)(Cbl + (size_t)row * ldc + col) = l0;
                *(uint32_t*)(Cbh + (size_t)(row + 8) * ldc + col) = h1;
                *(uint32_t*)(Cbl + (size_t)(row + 8) * ldc + col) = l1;
            }
        }
    }
}

// ---------------- flash attention (mma.sync, R9 version) ----------------
// Q,K bf16 hi/lo (3 S-passes, Q frags preloaded to regs);
// softmax via ex2.approx.f16x2 (P emerges packed fp16); V fp16 hi/lo (2 PV passes).
#define SRA   272
#define TEN_B (128 * SRA)
#define FSMEM (6 * TEN_B)

__global__ __launch_bounds__(256, 1)
void flash_mma(const __nv_bfloat16* __restrict__ qh, const __nv_bfloat16* __restrict__ ql,
               __nv_bfloat16* __restrict__ oh, __nv_bfloat16* __restrict__ ol)
{
    extern __shared__ __align__(16) char sm[];
    const uint32_t S0 = (uint32_t)__cvta_generic_to_shared(sm);
    const uint32_t oQh = 0, oQl = TEN_B, oKh = 2 * TEN_B, oKl = 3 * TEN_B,
                   oVh = 4 * TEN_B, oVl = 5 * TEN_B;

    const int tid = threadIdx.x, warp = tid >> 5, lane = tid & 31;
    const int lr = lane >> 2, lc = lane & 3;
    const int qt = blockIdx.x, h = blockIdx.y, b = blockIdx.z;
    const size_t rowbase = (size_t)(b * 2048 + h * 128) * 6144;

    const int arow = lane & 15, ahalf = (lane >> 4) * 16;
    const int brow = (lane & 7) + ((lane >> 4) << 3);
    const int bhalf = ((lane >> 3) & 1) * 16;

    auto issue_kv = [&](int t64, int buf) {
        #pragma unroll
        for (int t = 0; t < 16; t++) {
            int i = tid + t * 256;
            int sub = i >> 10;
            int j = i & 1023;
            int r = j >> 4, c = j & 15;
            int koff = (sub >> 1) ? 4096 : 2048;
            const __nv_bfloat16* base = (sub & 1) ? ql : qh;
            const __nv_bfloat16* src = base + rowbase
                + (size_t)(t64 * 4 + (r >> 4)) * 6144 + ((r & 15) << 7) + koff + c * 8;
            uint32_t off = (sub & 1) ? ((sub >> 1) ? oVl : oKl) : ((sub >> 1) ? oVh : oKh);
            CPA16(S0 + off + (buf * 64 + r) * SRA + c * 16, src);
        }
        CPA_COMMIT();
    };

    #pragma unroll
    for (int t = 0; t < 16; t++) {
        int i = tid + t * 256;
        int sub = i >> 11;
        int j = i & 2047;
        int r = j >> 4, c = j & 15;
        const __nv_bfloat16* src = (sub ? ql : qh) + rowbase
            + (size_t)(qt * 8 + (r >> 4)) * 6144 + ((r & 15) << 7) + c * 8;
        CPA16(S0 + (sub ? oQl : oQh) + r * SRA + c * 16, src);
    }
    CPA_COMMIT();

    const int nt = 2 * qt + 2;
    issue_kv(0, 0);

    float accO[16][4];
    #pragma unroll
    for (int ni = 0; ni < 16; ni++)
        #pragma unroll
        for (int q = 0; q < 4; q++) accO[ni][q] = 0.0f;
    float mrow[2] = {-1e30f, -1e30f}, lrow[2] = {0.0f, 0.0f};
    uint32_t qf[8][8];   // preloaded Q fragments: [dk][hi0..3, lo0..3]

    for (int t64 = 0; t64 < nt; t64++) {
        int buf = t64 & 1;
        if (t64 + 1 < nt) { issue_kv(t64 + 1, buf ^ 1); CPA_WAIT1(); }
        else              { CPA_WAIT0(); }
        __syncthreads();

        if (t64 == 0) {
            #pragma unroll
            for (int dk = 0; dk < 8; dk++) {
                uint32_t qa = S0 + oQh + (warp * 16 + arow) * SRA + dk * 32 + ahalf;
                LDSM4(qf[dk][0], qf[dk][1], qf[dk][2], qf[dk][3], qa);
                LDSM4(qf[dk][4], qf[dk][5], qf[dk][6], qf[dk][7], qa + TEN_B);
            }
        }

        const uint32_t kbB = buf * 64 * SRA;

        // ---- S = Q @ K^T (bf16 hi/lo, 3 passes) ----
        float sacc[8][4];
        #pragma unroll
        for (int ni = 0; ni < 8; ni++)
            #pragma unroll
            for (int q = 0; q < 4; q++) sacc[ni][q] = 0.0f;

        #pragma unroll
        for (int dk = 0; dk < 8; dk++) {
            #pragma unroll
            for (int np = 0; np < 4; np++) {
                uint32_t ka = S0 + oKh + kbB + (np * 16 + brow) * SRA + dk * 32 + bhalf;
                uint32_t bh0, bh1, bh2, bh3, bl0, bl1, bl2, bl3;
                LDSM4(bh0, bh1, bh2, bh3, ka);
                LDSM4(bl0, bl1, bl2, bl3, ka + TEN_B);
                MMA16816(sacc[2 * np], qf[dk][0], qf[dk][1], qf[dk][2], qf[dk][3], bh0, bh1);
                MMA16816(sacc[2 * np], qf[dk][0], qf[dk][1], qf[dk][2], qf[dk][3], bl0, bl1);
                MMA16816(sacc[2 * np], qf[dk][4], qf[dk][5], qf[dk][6], qf[dk][7], bh0, bh1);
                MMA16816(sacc[2 * np + 1], qf[dk][0], qf[dk][1], qf[dk][2], qf[dk][3], bh2, bh3);
                MMA16816(sacc[2 * np + 1], qf[dk][0], qf[dk][1], qf[dk][2], qf[dk][3], bl2, bl3);
                MMA16816(sacc[2 * np + 1], qf[dk][4], qf[dk][5], qf[dk][6], qf[dk][7], bh2, bh3);
            }
        }

        // ---- causal mask ----
        if (t64 >= 2 * qt) {
            #pragma unroll
            for (int ni = 0; ni < 8; ni++)
                #pragma unroll
                for (int q = 0; q < 4; q++) {
                    int col_g = t64 * 64 + ni * 8 + lc * 2 + (q & 1);
                    int row_g = qt * 128 + warp * 16 + lr + (q >> 1) * 8;
                    if (col_g > row_g) sacc[ni][q] = -1e30f;
                }
        }

        // ---- online softmax; P computed packed-fp16 via ex2.approx.f16x2 ----
        float corr[2];
        uint32_t ph[8][2];
        #pragma unroll
        for (int hf = 0; hf < 2; hf++) {
            float rm = -1e30f;
            #pragma unroll
            for (int ni = 0; ni < 8; ni++)
                rm = fmaxf(rm, fmaxf(sacc[ni][hf * 2], sacc[ni][hf * 2 + 1]));
            rm = fmaxf(rm, __shfl_xor_sync(0xffffffffu, rm, 1));
            rm = fmaxf(rm, __shfl_xor_sync(0xffffffffu, rm, 2));
            float mnew = fmaxf(mrow[hf], rm);
            corr[hf] = exp2f(mrow[hf] - mnew);
            mrow[hf] = mnew;
            float ls = 0.0f;
            #pragma unroll
            for (int ni = 0; ni < 8; ni++) {
                uint32_t p;
                EXP2PAIR(p, sacc[ni][hf * 2 + 1] - mnew, sacc[ni][hf * 2] - mnew);
                ph[ni][hf] = p;
                float2 f = __half22float2(*reinterpret_cast<__half2*>(&p));
                ls += f.x + f.y;
            }
            lrow[hf] = lrow[hf] * corr[hf] + ls;
        }
        #pragma unroll
        for (int ni = 0; ni < 16; ni++)
            #pragma unroll
            for (int q = 0; q < 4; q++) accO[ni][q] *= corr[q >> 1];

        // ---- O += P @ V (P fp16 packed from exp, V fp16 hi/lo -> 2 passes) ----
        #pragma unroll
        for (int j = 0; j < 4; j++) {
            uint32_t pa0 = ph[2 * j][0], pa1 = ph[2 * j][1];
            uint32_t pa2 = ph[2 * j + 1][0], pa3 = ph[2 * j + 1][1];
            #pragma unroll
            for (int n2 = 0; n2 < 8; n2++) {
                uint32_t va = S0 + oVh + kbB + (j * 16 + (lane & 15)) * SRA
                            + n2 * 32 + (lane >> 4) * 16;
                uint32_t vh0, vh1, vh2, vh3, vl0, vl1, vl2, vl3;
                LDSM4T(vh0, vh1, vh2, vh3, va);
                LDSM4T(vl0, vl1, vl2, vl3, va + TEN_B);
                MMAH16816(accO[2 * n2], pa0, pa1, pa2, pa3, vh0, vh1);
                MMAH16816(accO[2 * n2], pa0, pa1, pa2, pa3, vl0, vl1);
                MMAH16816(accO[2 * n2 + 1], pa0, pa1, pa2, pa3, vh2, vh3);
                MMAH16816(accO[2 * n2 + 1], pa0, pa1, pa2, pa3, vl2, vl3);
            }
        }
        __syncthreads();
    }

    // ---- normalize + write O (bf16 hi/lo, head-contiguous) ----
    float inv[2];
    #pragma unroll
    for (int hf = 0; hf < 2; hf++) {
        float ls = lrow[hf];
        ls += __shfl_xor_sync(0xffffffffu, ls, 1);
        ls += __shfl_xor_sync(0xffffffffu, ls, 2);
        inv[hf] = 1.0f / ls;
    }
    #pragma unroll
    for (int hf = 0; hf < 2; hf++) {
        int srow = qt * 128 + warp * 16 + lr + hf * 8;
        size_t base = ((size_t)(b * 16 + h) * 2048 + srow) << 7;
        #pragma unroll
        for (int ni = 0; ni < 16; ni++) {
            int d = ni * 8 + lc * 2;
            uint32_t hh, ll;
            split2u(accO[ni][hf * 2] * inv[hf], accO[ni][hf * 2 + 1] * inv[hf], hh, ll);
            *(uint32_t*)(oh + base + d) = hh;
            *(uint32_t*)(ol + base + d) = ll;
        }
    }
}

// ---------------------------------------------------------------------------
extern "C" void kernel_launch(void* const* d_in, const int* in_sizes, int n_in,
                              void* d_out, int out_size)
{
    (void)in_sizes; (void)n_in; (void)out_size;
    const float* x    = (const float*)d_in[0];
    const float* wqkv = (const float*)d_in[1];
    const float* wout = (const float*)d_in[2];
    float* out = (float*)d_out;

    __nv_bfloat16 *qkvh, *qkvl, *xh, *xl, *wqh, *wql, *woh, *wol, *oh, *ol;
    cudaGetSymbolAddress((void**)&qkvh, g_qkvh); cudaGetSymbolAddress((void**)&qkvl, g_qkvl);
    cudaGetSymbolAddress((void**)&xh, g_xh);     cudaGetSymbolAddress((void**)&xl, g_xl);
    cudaGetSymbolAddress((void**)&wqh, g_wqh);   cudaGetSymbolAddress((void**)&wql, g_wql);
    cudaGetSymbolAddress((void**)&woh, g_woh);   cudaGetSymbolAddress((void**)&wol, g_wol);
    cudaGetSymbolAddress((void**)&oh, g_oh);     cudaGetSymbolAddress((void**)&ol, g_ol);

    cudaFuncSetAttribute(gemm_mma_bf16x3,
                         cudaFuncAttributeMaxDynamicSharedMemorySize, GSMEM);
    cudaFuncSetAttribute(flash_mma,
                         cudaFuncAttributeMaxDynamicSharedMemorySize, FSMEM);

    ksplit<<<(M_TOT * GK / 4 + 255) / 256, 256>>>(x, xh, xl, M_TOT * GK / 4);
    ksplitT<<<dim3(NQKV / 32, GK / 32), dim3(32, 8)>>>(wqkv, wqh, wql, GK, NQKV);
    ksplitT<<<dim3(GK / 32, GK / 32), dim3(32, 8)>>>(wout, woh, wol, GK, GK);

    gemm_mma_bf16x3<<<dim3(NQKV / 128, M_TOT / 128), 256, GSMEM>>>(
        xh, xl, wqh, wql, nullptr, qkvh, qkvl, NQKV, 1);

    flash_mma<<<dim3(16, 16, 4), 256, FSMEM>>>(qkvh, qkvl, oh, ol);

    gemm_mma_bf16x3<<<dim3(GK / 128, M_TOT / 128), 256, GSMEM>>>(
        oh, ol, woh, wol, out, nullptr, nullptr, GK, 0);
}

// round 11
// speedup vs baseline: 2.4197x; 2.1260x over previous
#include <cuda_runtime.h>
#include <cuda_bf16.h>
#include <cuda_fp16.h>
#include <cstdint>
#include <math.h>

#define M_TOT 8192
#define NQKV  6144
#define GK    2048

// ---------------- device scratch (all fp16 single precision) ----------------
__device__ __half g_qkv[(size_t)M_TOT * NQKV];   // Q (pre-scaled) | K | V
__device__ __half g_xF[(size_t)M_TOT * GK];
__device__ __half g_wqF[(size_t)NQKV * GK];      // W_qkv^T
__device__ __half g_woF[(size_t)GK * GK];        // W_out^T
__device__ __half g_oF[(size_t)M_TOT * GK];      // attention out

#define QSCALE (0.08838834764831845f * 1.4426950408889634f)

// ---------------- helpers ----------------
#define CPA16(dst, src) \
    asm volatile("cp.async.cg.shared.global [%0], [%1], 16;" :: "r"(dst), "l"(src))
#define CPA_COMMIT() asm volatile("cp.async.commit_group;")
#define CPA_WAIT1()  asm volatile("cp.async.wait_group 1;")
#define CPA_WAIT0()  asm volatile("cp.async.wait_group 0;")

#define MMAH16816(ac, a0, a1, a2, a3, b0, b1) \
    asm volatile("mma.sync.aligned.m16n8k16.row.col.f32.f16.f16.f32 " \
        "{%0,%1,%2,%3},{%4,%5,%6,%7},{%8,%9},{%0,%1,%2,%3};" \
        : "+f"((ac)[0]), "+f"((ac)[1]), "+f"((ac)[2]), "+f"((ac)[3]) \
        : "r"(a0), "r"(a1), "r"(a2), "r"(a3), "r"(b0), "r"(b1))

#define LDSM4(r0, r1, r2, r3, addr) \
    asm volatile("ldmatrix.sync.aligned.m8n8.x4.shared.b16 {%0,%1,%2,%3}, [%4];" \
        : "=r"(r0), "=r"(r1), "=r"(r2), "=r"(r3) : "r"(addr))
#define LDSM4T(r0, r1, r2, r3, addr) \
    asm volatile("ldmatrix.sync.aligned.m8n8.x4.trans.shared.b16 {%0,%1,%2,%3}, [%4];" \
        : "=r"(r0), "=r"(r1), "=r"(r2), "=r"(r3) : "r"(addr))

// pack two fp32 -> fp16x2 (x1 -> hi half, x0 -> lo half)
#define PACKH(d, x1, x0) \
    asm("cvt.rn.f16x2.f32 %0, %1, %2;" : "=r"(d) : "f"(x1), "f"(x0))

// pack then exp2 both halves in one MUFU op
#define EXP2PAIR(d, x1, x0) do {                                     \
    uint32_t _t;                                                     \
    asm("cvt.rn.f16x2.f32 %0, %1, %2;" : "=r"(_t) : "f"(x1), "f"(x0)); \
    asm("ex2.approx.f16x2 %0, %1;" : "=r"(d) : "r"(_t));             \
} while (0)

// ---------------- conversion kernels ----------------
__global__ void khalf(const float* __restrict__ in, __half* __restrict__ out, int n4)
{
    int i = blockIdx.x * blockDim.x + threadIdx.x;
    if (i >= n4) return;
    float4 v = ((const float4*)in)[i];
    uint2 o;
    PACKH(o.x, v.y, v.x);
    PACKH(o.y, v.w, v.z);
    ((uint2*)out)[i] = o;
}

// in [K, N] row-major -> out^T [N, K] fp16
__global__ void khalfT(const float* __restrict__ in, __half* __restrict__ outT, int K, int N)
{
    __shared__ float t[32][33];
    int n0 = blockIdx.x * 32, k0 = blockIdx.y * 32;
    int tx = threadIdx.x, ty = threadIdx.y;
    #pragma unroll
    for (int j = 0; j < 32; j += 8)
        t[ty + j][tx] = in[(size_t)(k0 + ty + j) * N + n0 + tx];
    __syncthreads();
    #pragma unroll
    for (int j = 0; j < 32; j += 8)
        outT[(size_t)(n0 + ty + j) * K + k0 + tx] = __float2half(t[tx][ty + j]);
}

// ---------------- fp16 single-pass GEMM ----------------
// C[M,N] = A[M,K] @ B[Ntot,K]^T. Block 128x128x32, 8 warps 64x32, 2-stage cp.async.
#define SROW    80
#define TILE_B  (128 * SROW)        // 10240
#define STAGE_B (2 * TILE_B)        // 20480: A | B
#define GSMEM   (2 * STAGE_B)       // 40960

__global__ __launch_bounds__(256)
void gemm_fp16(const __half* __restrict__ A, const __half* __restrict__ B,
               float* __restrict__ C, __half* __restrict__ Ch,
               int ldc, int mode)
{
    extern __shared__ __align__(16) char smem[];
    const uint32_t sbase = (uint32_t)__cvta_generic_to_shared(smem);
    const int tid  = threadIdx.x;
    const int warp = tid >> 5, lane = tid & 31;
    const int m0 = blockIdx.y * 128, n0 = blockIdx.x * 128;
    const int wm = (warp & 1) * 64, wn = (warp >> 1) * 32;

    auto issue = [&](int st, int k0) {
        uint32_t dbase = sbase + st * STAGE_B;
        #pragma unroll
        for (int t = 0; t < 4; t++) {
            int i = tid + t * 256;
            int sub = i >> 9;
            int j = i & 511;
            int r = j >> 2, c = j & 3;
            const __half* g = (sub == 0)
                ? A + (size_t)(m0 + r) * GK + k0 + c * 8
                : B + (size_t)(n0 + r) * GK + k0 + c * 8;
            CPA16(dbase + sub * TILE_B + r * SROW + c * 16, (const void*)g);
        }
        CPA_COMMIT();
    };

    float acc[4][4][4];
    #pragma unroll
    for (int mi = 0; mi < 4; mi++)
        #pragma unroll
        for (int ni = 0; ni < 4; ni++)
            #pragma unroll
            for (int q = 0; q < 4; q++) acc[mi][ni][q] = 0.0f;

    issue(0, 0);

    const int lr = lane >> 2;
    const int arow = lane & 15, ahalf = (lane >> 4) * 16;
    const int brow = (lane & 7) + ((lane >> 4) << 3);
    const int bhalf = ((lane >> 3) & 1) * 16;

    for (int ch = 0; ch < 64; ch++) {
        int buf = ch & 1;
        if (ch < 63) { issue(buf ^ 1, (ch + 1) * 32); CPA_WAIT1(); }
        else         { CPA_WAIT0(); }
        __syncthreads();

        const uint32_t sA = sbase + buf * STAGE_B;
        const uint32_t sB = sA + TILE_B;

        #pragma unroll
        for (int k16 = 0; k16 < 2; k16++) {
            const int kb2 = k16 * 32;
            uint32_t bh[4][2];
            #pragma unroll
            for (int np = 0; np < 2; np++) {
                uint32_t ba = (wn + np * 16 + brow) * SROW + kb2 + bhalf;
                LDSM4(bh[2 * np][0], bh[2 * np][1], bh[2 * np + 1][0], bh[2 * np + 1][1],
                      sB + ba);
            }
            #pragma unroll
            for (int mi = 0; mi < 4; mi++) {
                uint32_t aa = (wm + mi * 16 + arow) * SROW + kb2 + ahalf;
                uint32_t a0, a1, a2, a3;
                LDSM4(a0, a1, a2, a3, sA + aa);
                #pragma unroll
                for (int ni = 0; ni < 4; ni++)
                    MMAH16816(acc[mi][ni], a0, a1, a2, a3, bh[ni][0], bh[ni][1]);
            }
        }
        __syncthreads();
    }

    #pragma unroll
    for (int mi = 0; mi < 4; mi++) {
        int row = m0 + wm + mi * 16 + lr;
        #pragma unroll
        for (int ni = 0; ni < 4; ni++) {
            int col = n0 + wn + ni * 8 + (lane & 3) * 2;
            if (mode == 0) {
                float* p0 = C + (size_t)row * ldc + col;
                float* p1 = C + (size_t)(row + 8) * ldc + col;
                p0[0] = acc[mi][ni][0]; p0[1] = acc[mi][ni][1];
                p1[0] = acc[mi][ni][2]; p1[1] = acc[mi][ni][3];
            } else {
                float sc = (col < 2048) ? QSCALE : 1.0f;
                uint32_t d0, d1;
                PACKH(d0, acc[mi][ni][1] * sc, acc[mi][ni][0] * sc);
                PACKH(d1, acc[mi][ni][3] * sc, acc[mi][ni][2] * sc);
                *(uint32_t*)(Ch + (size_t)row * ldc + col) = d0;
                *(uint32_t*)(Ch + (size_t)(row + 8) * ldc + col) = d1;
            }
        }
    }
}

// ---------------- flash attention (fp16 single, mma.sync) ----------------
// Q,K,V,P all fp16; 1 S-pass + 1 PV-pass; exp via ex2.approx.f16x2.
#define SRA   272
#define TEN_B (128 * SRA)          // 34816
#define FSMEM (3 * TEN_B)          // 104448: Q | K(2x64) | V(2x64)

__global__ __launch_bounds__(256, 1)
void flash_fp16(const __half* __restrict__ qkv, __half* __restrict__ o)
{
    extern __shared__ __align__(16) char sm[];
    const uint32_t S0 = (uint32_t)__cvta_generic_to_shared(sm);
    const uint32_t oQ = 0, oK = TEN_B, oV = 2 * TEN_B;

    const int tid = threadIdx.x, warp = tid >> 5, lane = tid & 31;
    const int lr = lane >> 2, lc = lane & 3;
    const int qt = blockIdx.x, h = blockIdx.y, b = blockIdx.z;
    const size_t rowbase = (size_t)(b * 2048 + h * 128) * 6144;

    const int arow = lane & 15, ahalf = (lane >> 4) * 16;
    const int brow = (lane & 7) + ((lane >> 4) << 3);
    const int bhalf = ((lane >> 3) & 1) * 16;

    auto issue_kv = [&](int t64, int buf) {
        #pragma unroll
        for (int t = 0; t < 8; t++) {
            int i = tid + t * 256;
            int sub = i >> 10;                 // 0 K, 1 V
            int j = i & 1023;
            int r = j >> 4, c = j & 15;
            const __half* src = qkv + rowbase
                + (size_t)(t64 * 4 + (r >> 4)) * 6144 + ((r & 15) << 7)
                + (sub ? 4096 : 2048) + c * 8;
            uint32_t off = sub ? oV : oK;
            CPA16(S0 + off + (buf * 64 + r) * SRA + c * 16, src);
        }
        CPA_COMMIT();
    };

    // Q load (group 0): 128 rows x 16 chunks
    #pragma unroll
    for (int t = 0; t < 8; t++) {
        int i = tid + t * 256;
        int r = i >> 4, c = i & 15;
        const __half* src = qkv + rowbase
            + (size_t)(qt * 8 + (r >> 4)) * 6144 + ((r & 15) << 7) + c * 8;
        CPA16(S0 + oQ + r * SRA + c * 16, src);
    }
    CPA_COMMIT();

    const int nt = 2 * qt + 2;
    issue_kv(0, 0);

    float accO[16][4];
    #pragma unroll
    for (int ni = 0; ni < 16; ni++)
        #pragma unroll
        for (int q = 0; q < 4; q++) accO[ni][q] = 0.0f;
    float mrow[2] = {-1e30f, -1e30f}, lrow[2] = {0.0f, 0.0f};
    uint32_t qf[8][4];   // preloaded Q fragments

    for (int t64 = 0; t64 < nt; t64++) {
        int buf = t64 & 1;
        if (t64 + 1 < nt) { issue_kv(t64 + 1, buf ^ 1); CPA_WAIT1(); }
        else              { CPA_WAIT0(); }
        __syncthreads();

        if (t64 == 0) {
            #pragma unroll
            for (int dk = 0; dk < 8; dk++) {
                uint32_t qa = S0 + oQ + (warp * 16 + arow) * SRA + dk * 32 + ahalf;
                LDSM4(qf[dk][0], qf[dk][1], qf[dk][2], qf[dk][3], qa);
            }
        }

        const uint32_t kbB = buf * 64 * SRA;

        // ---- S = Q @ K^T (single fp16 pass) ----
        float sacc[8][4];
        #pragma unroll
        for (int ni = 0; ni < 8; ni++)
            #pragma unroll
            for (int q = 0; q < 4; q++) sacc[ni][q] = 0.0f;

        #pragma unroll
        for (int dk = 0; dk < 8; dk++) {
            #pragma unroll
            for (int np = 0; np < 4; np++) {
                uint32_t ka = S0 + oK + kbB + (np * 16 + brow) * SRA + dk * 32 + bhalf;
                uint32_t b0, b1, b2, b3;
                LDSM4(b0, b1, b2, b3, ka);
                MMAH16816(sacc[2 * np], qf[dk][0], qf[dk][1], qf[dk][2], qf[dk][3], b0, b1);
                MMAH16816(sacc[2 * np + 1], qf[dk][0], qf[dk][1], qf[dk][2], qf[dk][3], b2, b3);
            }
        }

        // ---- causal mask ----
        if (t64 >= 2 * qt) {
            #pragma unroll
            for (int ni = 0; ni < 8; ni++)
                #pragma unroll
                for (int q = 0; q < 4; q++) {
                    int col_g = t64 * 64 + ni * 8 + lc * 2 + (q & 1);
                    int row_g = qt * 128 + warp * 16 + lr + (q >> 1) * 8;
                    if (col_g > row_g) sacc[ni][q] = -1e30f;
                }
        }

        // ---- online softmax; P packed fp16 via ex2.approx.f16x2 ----
        float corr[2];
        uint32_t ph[8][2];
        #pragma unroll
        for (int hf = 0; hf < 2; hf++) {
            float rm = -1e30f;
            #pragma unroll
            for (int ni = 0; ni < 8; ni++)
                rm = fmaxf(rm, fmaxf(sacc[ni][hf * 2], sacc[ni][hf * 2 + 1]));
            rm = fmaxf(rm, __shfl_xor_sync(0xffffffffu, rm, 1));
            rm = fmaxf(rm, __shfl_xor_sync(0xffffffffu, rm, 2));
            float mnew = fmaxf(mrow[hf], rm);
            corr[hf] = exp2f(mrow[hf] - mnew);
            mrow[hf] = mnew;
            float ls = 0.0f;
            #pragma unroll
            for (int ni = 0; ni < 8; ni++) {
                uint32_t p;
                EXP2PAIR(p, sacc[ni][hf * 2 + 1] - mnew, sacc[ni][hf * 2] - mnew);
                ph[ni][hf] = p;
                float2 f = __half22float2(*reinterpret_cast<__half2*>(&p));
                ls += f.x + f.y;
            }
            lrow[hf] = lrow[hf] * corr[hf] + ls;
        }
        #pragma unroll
        for (int ni = 0; ni < 16; ni++)
            #pragma unroll
            for (int q = 0; q < 4; q++) accO[ni][q] *= corr[q >> 1];

        // ---- O += P @ V (single fp16 pass) ----
        #pragma unroll
        for (int j = 0; j < 4; j++) {
            uint32_t pa0 = ph[2 * j][0], pa1 = ph[2 * j][1];
            uint32_t pa2 = ph[2 * j + 1][0], pa3 = ph[2 * j + 1][1];
            #pragma unroll
            for (int n2 = 0; n2 < 8; n2++) {
                uint32_t va = S0 + oV + kbB + (j * 16 + (lane & 15)) * SRA
                            + n2 * 32 + (lane >> 4) * 16;
                uint32_t v0, v1, v2, v3;
                LDSM4T(v0, v1, v2, v3, va);
                MMAH16816(accO[2 * n2], pa0, pa1, pa2, pa3, v0, v1);
                MMAH16816(accO[2 * n2 + 1], pa0, pa1, pa2, pa3, v2, v3);
            }
        }
        __syncthreads();
    }

    // ---- normalize + write O (fp16, head-contiguous) ----
    float inv[2];
    #pragma unroll
    for (int hf = 0; hf < 2; hf++) {
        float ls = lrow[hf];
        ls += __shfl_xor_sync(0xffffffffu, ls, 1);
        ls += __shfl_xor_sync(0xffffffffu, ls, 2);
        inv[hf] = 1.0f / ls;
    }
    #pragma unroll
    for (int hf = 0; hf < 2; hf++) {
        int srow = qt * 128 + warp * 16 + lr + hf * 8;
        size_t base = ((size_t)(b * 16 + h) * 2048 + srow) << 7;
        #pragma unroll
        for (int ni = 0; ni < 16; ni++) {
            int d = ni * 8 + lc * 2;
            uint32_t hh;
            PACKH(hh, accO[ni][hf * 2 + 1] * inv[hf], accO[ni][hf * 2] * inv[hf]);
            *(uint32_t*)(o + base + d) = hh;
        }
    }
}

// ---------------------------------------------------------------------------
extern "C" void kernel_launch(void* const* d_in, const int* in_sizes, int n_in,
                              void* d_out, int out_size)
{
    (void)in_sizes; (void)n_in; (void)out_size;
    const float* x    = (const float*)d_in[0];
    const float* wqkv = (const float*)d_in[1];
    const float* wout = (const float*)d_in[2];
    float* out = (float*)d_out;

    __half *qkv, *xF, *wqF, *woF, *oF;
    cudaGetSymbolAddress((void**)&qkv, g_qkv);
    cudaGetSymbolAddress((void**)&xF, g_xF);
    cudaGetSymbolAddress((void**)&wqF, g_wqF);
    cudaGetSymbolAddress((void**)&woF, g_woF);
    cudaGetSymbolAddress((void**)&oF, g_oF);

    cudaFuncSetAttribute(gemm_fp16,
                         cudaFuncAttributeMaxDynamicSharedMemorySize, GSMEM);
    cudaFuncSetAttribute(flash_fp16,
                         cudaFuncAttributeMaxDynamicSharedMemorySize, FSMEM);

    khalf<<<(M_TOT * GK / 4 + 255) / 256, 256>>>(x, xF, M_TOT * GK / 4);
    khalfT<<<dim3(NQKV / 32, GK / 32), dim3(32, 8)>>>(wqkv, wqF, GK, NQKV);
    khalfT<<<dim3(GK / 32, GK / 32), dim3(32, 8)>>>(wout, woF, GK, GK);

    // 1) QKV projection -> fp16 (Q pre-scaled)
    gemm_fp16<<<dim3(NQKV / 128, M_TOT / 128), 256, GSMEM>>>(
        xF, wqF, nullptr, qkv, NQKV, 1);

    // 2) causal attention (all fp16) -> fp16 O
    flash_fp16<<<dim3(16, 16, 4), 256, FSMEM>>>(qkv, oF);

    // 3) output projection -> fp32 out
    gemm_fp16<<<dim3(GK / 128, M_TOT / 128), 256, GSMEM>>>(
        oF, woF, out, nullptr, GK, 0);
}

// round 13
// speedup vs baseline: 2.6047x; 1.0765x over previous
#include <cuda_runtime.h>
#include <cuda_bf16.h>
#include <cuda_fp16.h>
#include <cstdint>
#include <math.h>

#define M_TOT 8192
#define NQKV  6144
#define GK    2048

// ---------------- device scratch (all fp16 single precision) ----------------
__device__ __half g_qkv[(size_t)M_TOT * NQKV];   // Q (pre-scaled) | K | V
__device__ __half g_xF[(size_t)M_TOT * GK];
__device__ __half g_wqF[(size_t)NQKV * GK];      // W_qkv^T
__device__ __half g_woF[(size_t)GK * GK];        // W_out^T
__device__ __half g_oF[(size_t)M_TOT * GK];      // attention out

#define QSCALE (0.08838834764831845f * 1.4426950408889634f)

// ---------------- helpers ----------------
#define CPA16(dst, src) \
    asm volatile("cp.async.cg.shared.global [%0], [%1], 16;" :: "r"(dst), "l"(src))
#define CPA_COMMIT() asm volatile("cp.async.commit_group;")
#define CPA_WAIT2()  asm volatile("cp.async.wait_group 2;")
#define CPA_WAIT1()  asm volatile("cp.async.wait_group 1;")
#define CPA_WAIT0()  asm volatile("cp.async.wait_group 0;")

#define MMAH16816(ac, a0, a1, a2, a3, b0, b1) \
    asm volatile("mma.sync.aligned.m16n8k16.row.col.f32.f16.f16.f32 " \
        "{%0,%1,%2,%3},{%4,%5,%6,%7},{%8,%9},{%0,%1,%2,%3};" \
        : "+f"((ac)[0]), "+f"((ac)[1]), "+f"((ac)[2]), "+f"((ac)[3]) \
        : "r"(a0), "r"(a1), "r"(a2), "r"(a3), "r"(b0), "r"(b1))

#define LDSM4(r0, r1, r2, r3, addr) \
    asm volatile("ldmatrix.sync.aligned.m8n8.x4.shared.b16 {%0,%1,%2,%3}, [%4];" \
        : "=r"(r0), "=r"(r1), "=r"(r2), "=r"(r3) : "r"(addr))
#define LDSM4T(r0, r1, r2, r3, addr) \
    asm volatile("ldmatrix.sync.aligned.m8n8.x4.trans.shared.b16 {%0,%1,%2,%3}, [%4];" \
        : "=r"(r0), "=r"(r1), "=r"(r2), "=r"(r3) : "r"(addr))

// pack two fp32 -> fp16x2 (x1 -> hi half, x0 -> lo half)
#define PACKH(d, x1, x0) \
    asm("cvt.rn.f16x2.f32 %0, %1, %2;" : "=r"(d) : "f"(x1), "f"(x0))

// pack then exp2 both halves in one MUFU op
#define EXP2PAIR(d, x1, x0) do {                                     \
    uint32_t _t;                                                     \
    asm("cvt.rn.f16x2.f32 %0, %1, %2;" : "=r"(_t) : "f"(x1), "f"(x0)); \
    asm("ex2.approx.f16x2 %0, %1;" : "=r"(d) : "r"(_t));             \
} while (0)

// ---------------- conversion kernels ----------------
__global__ void khalf(const float* __restrict__ in, __half* __restrict__ out, int n4)
{
    int i = blockIdx.x * blockDim.x + threadIdx.x;
    if (i >= n4) return;
    float4 v = ((const float4*)in)[i];
    uint2 o;
    PACKH(o.x, v.y, v.x);
    PACKH(o.y, v.w, v.z);
    ((uint2*)out)[i] = o;
}

// in [K, N] row-major -> out^T [N, K] fp16
__global__ void khalfT(const float* __restrict__ in, __half* __restrict__ outT, int K, int N)
{
    __shared__ float t[32][33];
    int n0 = blockIdx.x * 32, k0 = blockIdx.y * 32;
    int tx = threadIdx.x, ty = threadIdx.y;
    #pragma unroll
    for (int j = 0; j < 32; j += 8)
        t[ty + j][tx] = in[(size_t)(k0 + ty + j) * N + n0 + tx];
    __syncthreads();
    #pragma unroll
    for (int j = 0; j < 32; j += 8)
        outT[(size_t)(n0 + ty + j) * K + k0 + tx] = __float2half(t[tx][ty + j]);
}

// ---------------- fp16 single-pass GEMM ----------------
// C[M,N] = A[M,K] @ B[Ntot,K]^T. Block 128x128x32, 8 warps 64x32,
// 3-stage cp.async pipeline (schedule change only vs R11).
#define SROW    80
#define TILE_B  (128 * SROW)        // 10240
#define STAGE_B (2 * TILE_B)        // 20480: A | B
#define GSMEM   (3 * STAGE_B)       // 61440

__global__ __launch_bounds__(256)
void gemm_fp16(const __half* __restrict__ A, const __half* __restrict__ B,
               float* __restrict__ C, __half* __restrict__ Ch,
               int ldc, int mode)
{
    extern __shared__ __align__(16) char smem[];
    const uint32_t sbase = (uint32_t)__cvta_generic_to_shared(smem);
    const int tid  = threadIdx.x;
    const int warp = tid >> 5, lane = tid & 31;
    const int m0 = blockIdx.y * 128, n0 = blockIdx.x * 128;
    const int wm = (warp & 1) * 64, wn = (warp >> 1) * 32;

    auto issue = [&](int st, int k0) {
        uint32_t dbase = sbase + st * STAGE_B;
        #pragma unroll
        for (int t = 0; t < 4; t++) {
            int i = tid + t * 256;
            int sub = i >> 9;
            int j = i & 511;
            int r = j >> 2, c = j & 3;
            const __half* g = (sub == 0)
                ? A + (size_t)(m0 + r) * GK + k0 + c * 8
                : B + (size_t)(n0 + r) * GK + k0 + c * 8;
            CPA16(dbase + sub * TILE_B + r * SROW + c * 16, (const void*)g);
        }
        CPA_COMMIT();
    };

    float acc[4][4][4];
    #pragma unroll
    for (int mi = 0; mi < 4; mi++)
        #pragma unroll
        for (int ni = 0; ni < 4; ni++)
            #pragma unroll
            for (int q = 0; q < 4; q++) acc[mi][ni][q] = 0.0f;

    issue(0, 0);
    issue(1, 32);

    const int lr = lane >> 2;
    const int arow = lane & 15, ahalf = (lane >> 4) * 16;
    const int brow = (lane & 7) + ((lane >> 4) << 3);
    const int bhalf = ((lane >> 3) & 1) * 16;

    for (int ch = 0; ch < 64; ch++) {
        int buf = ch % 3;
        if (ch + 2 < 64)      { issue((ch + 2) % 3, (ch + 2) * 32); CPA_WAIT2(); }
        else if (ch + 1 < 64) { CPA_WAIT1(); }
        else                  { CPA_WAIT0(); }
        __syncthreads();

        const uint32_t sA = sbase + buf * STAGE_B;
        const uint32_t sB = sA + TILE_B;

        #pragma unroll
        for (int k16 = 0; k16 < 2; k16++) {
            const int kb2 = k16 * 32;
            uint32_t bh[4][2];
            #pragma unroll
            for (int np = 0; np < 2; np++) {
                uint32_t ba = (wn + np * 16 + brow) * SROW + kb2 + bhalf;
                LDSM4(bh[2 * np][0], bh[2 * np][1], bh[2 * np + 1][0], bh[2 * np + 1][1],
                      sB + ba);
            }
            #pragma unroll
            for (int mi = 0; mi < 4; mi++) {
                uint32_t aa = (wm + mi * 16 + arow) * SROW + kb2 + ahalf;
                uint32_t a0, a1, a2, a3;
                LDSM4(a0, a1, a2, a3, sA + aa);
                #pragma unroll
                for (int ni = 0; ni < 4; ni++)
                    MMAH16816(acc[mi][ni], a0, a1, a2, a3, bh[ni][0], bh[ni][1]);
            }
        }
        __syncthreads();
    }

    #pragma unroll
    for (int mi = 0; mi < 4; mi++) {
        int row = m0 + wm + mi * 16 + lr;
        #pragma unroll
        for (int ni = 0; ni < 4; ni++) {
            int col = n0 + wn + ni * 8 + (lane & 3) * 2;
            if (mode == 0) {
                float* p0 = C + (size_t)row * ldc + col;
                float* p1 = C + (size_t)(row + 8) * ldc + col;
                p0[0] = acc[mi][ni][0]; p0[1] = acc[mi][ni][1];
                p1[0] = acc[mi][ni][2]; p1[1] = acc[mi][ni][3];
            } else {
                float sc = (col < 2048) ? QSCALE : 1.0f;
                uint32_t d0, d1;
                PACKH(d0, acc[mi][ni][1] * sc, acc[mi][ni][0] * sc);
                PACKH(d1, acc[mi][ni][3] * sc, acc[mi][ni][2] * sc);
                *(uint32_t*)(Ch + (size_t)row * ldc + col) = d0;
                *(uint32_t*)(Ch + (size_t)(row + 8) * ldc + col) = d1;
            }
        }
    }
}

// ---------------- flash attention (fp16 single, mma.sync) ----------------
// Q,K,V,P all fp16; 1 S-pass + 1 PV-pass; exp via ex2.approx.f16x2.
#define SRA   272
#define TEN_B (128 * SRA)          // 34816
#define FSMEM (3 * TEN_B)          // 104448: Q | K(2x64) | V(2x64)

__global__ __launch_bounds__(256, 1)
void flash_fp16(const __half* __restrict__ qkv, __half* __restrict__ o)
{
    extern __shared__ __align__(16) char sm[];
    const uint32_t S0 = (uint32_t)__cvta_generic_to_shared(sm);
    const uint32_t oQ = 0, oK = TEN_B, oV = 2 * TEN_B;

    const int tid = threadIdx.x, warp = tid >> 5, lane = tid & 31;
    const int lr = lane >> 2, lc = lane & 3;
    const int qt = blockIdx.x, h = blockIdx.y, b = blockIdx.z;
    const size_t rowbase = (size_t)(b * 2048 + h * 128) * 6144;

    const int arow = lane & 15, ahalf = (lane >> 4) * 16;
    const int brow = (lane & 7) + ((lane >> 4) << 3);
    const int bhalf = ((lane >> 3) & 1) * 16;

    auto issue_kv = [&](int t64, int buf) {
        #pragma unroll
        for (int t = 0; t < 8; t++) {
            int i = tid + t * 256;
            int sub = i >> 10;                 // 0 K, 1 V
            int j = i & 1023;
            int r = j >> 4, c = j & 15;
            const __half* src = qkv + rowbase
                + (size_t)(t64 * 4 + (r >> 4)) * 6144 + ((r & 15) << 7)
                + (sub ? 4096 : 2048) + c * 8;
            uint32_t off = sub ? oV : oK;
            CPA16(S0 + off + (buf * 64 + r) * SRA + c * 16, src);
        }
        CPA_COMMIT();
    };

    // Q load (group 0): 128 rows x 16 chunks
    #pragma unroll
    for (int t = 0; t < 8; t++) {
        int i = tid + t * 256;
        int r = i >> 4, c = i & 15;
        const __half* src = qkv + rowbase
            + (size_t)(qt * 8 + (r >> 4)) * 6144 + ((r & 15) << 7) + c * 8;
        CPA16(S0 + oQ + r * SRA + c * 16, src);
    }
    CPA_COMMIT();

    const int nt = 2 * qt + 2;
    issue_kv(0, 0);

    float accO[16][4];
    #pragma unroll
    for (int ni = 0; ni < 16; ni++)
        #pragma unroll
        for (int q = 0; q < 4; q++) accO[ni][q] = 0.0f;
    float mrow[2] = {-1e30f, -1e30f}, lrow[2] = {0.0f, 0.0f};
    uint32_t qf[8][4];   // preloaded Q fragments

    for (int t64 = 0; t64 < nt; t64++) {
        int buf = t64 & 1;
        if (t64 + 1 < nt) { issue_kv(t64 + 1, buf ^ 1); CPA_WAIT1(); }
        else              { CPA_WAIT0(); }
        __syncthreads();

        if (t64 == 0) {
            #pragma unroll
            for (int dk = 0; dk < 8; dk++) {
                uint32_t qa = S0 + oQ + (warp * 16 + arow) * SRA + dk * 32 + ahalf;
                LDSM4(qf[dk][0], qf[dk][1], qf[dk][2], qf[dk][3], qa);
            }
        }

        const uint32_t kbB = buf * 64 * SRA;

        // ---- S = Q @ K^T (single fp16 pass) ----
        float sacc[8][4];
        #pragma unroll
        for (int ni = 0; ni < 8; ni++)
            #pragma unroll
            for (int q = 0; q < 4; q++) sacc[ni][q] = 0.0f;

        #pragma unroll
        for (int dk = 0; dk < 8; dk++) {
            #pragma unroll
            for (int np = 0; np < 4; np++) {
                uint32_t ka = S0 + oK + kbB + (np * 16 + brow) * SRA + dk * 32 + bhalf;
                uint32_t b0, b1, b2, b3;
                LDSM4(b0, b1, b2, b3, ka);
                MMAH16816(sacc[2 * np], qf[dk][0], qf[dk][1], qf[dk][2], qf[dk][3], b0, b1);
                MMAH16816(sacc[2 * np + 1], qf[dk][0], qf[dk][1], qf[dk][2], qf[dk][3], b2, b3);
            }
        }

        // ---- causal mask ----
        if (t64 >= 2 * qt) {
            #pragma unroll
            for (int ni = 0; ni < 8; ni++)
                #pragma unroll
                for (int q = 0; q < 4; q++) {
                    int col_g = t64 * 64 + ni * 8 + lc * 2 + (q & 1);
                    int row_g = qt * 128 + warp * 16 + lr + (q >> 1) * 8;
                    if (col_g > row_g) sacc[ni][q] = -1e30f;
                }
        }

        // ---- online softmax; P packed fp16 via ex2.approx.f16x2 ----
        float corr[2];
        uint32_t ph[8][2];
        #pragma unroll
        for (int hf = 0; hf < 2; hf++) {
            float rm = -1e30f;
            #pragma unroll
            for (int ni = 0; ni < 8; ni++)
                rm = fmaxf(rm, fmaxf(sacc[ni][hf * 2], sacc[ni][hf * 2 + 1]));
            rm = fmaxf(rm, __shfl_xor_sync(0xffffffffu, rm, 1));
            rm = fmaxf(rm, __shfl_xor_sync(0xffffffffu, rm, 2));
            float mnew = fmaxf(mrow[hf], rm);
            corr[hf] = exp2f(mrow[hf] - mnew);
            mrow[hf] = mnew;
            float ls = 0.0f;
            #pragma unroll
            for (int ni = 0; ni < 8; ni++) {
                uint32_t p;
                EXP2PAIR(p, sacc[ni][hf * 2 + 1] - mnew, sacc[ni][hf * 2] - mnew);
                ph[ni][hf] = p;
                float2 f = __half22float2(*reinterpret_cast<__half2*>(&p));
                ls += f.x + f.y;
            }
            lrow[hf] = lrow[hf] * corr[hf] + ls;
        }
        #pragma unroll
        for (int ni = 0; ni < 16; ni++)
            #pragma unroll
            for (int q = 0; q < 4; q++) accO[ni][q] *= corr[q >> 1];

        // ---- O += P @ V (single fp16 pass) ----
        #pragma unroll
        for (int j = 0; j < 4; j++) {
            uint32_t pa0 = ph[2 * j][0], pa1 = ph[2 * j][1];
            uint32_t pa2 = ph[2 * j + 1][0], pa3 = ph[2 * j + 1][1];
            #pragma unroll
            for (int n2 = 0; n2 < 8; n2++) {
                uint32_t va = S0 + oV + kbB + (j * 16 + (lane & 15)) * SRA
                            + n2 * 32 + (lane >> 4) * 16;
                uint32_t v0, v1, v2, v3;
                LDSM4T(v0, v1, v2, v3, va);
                MMAH16816(accO[2 * n2], pa0, pa1, pa2, pa3, v0, v1);
                MMAH16816(accO[2 * n2 + 1], pa0, pa1, pa2, pa3, v2, v3);
            }
        }
        __syncthreads();
    }

    // ---- normalize + write O (fp16, head-contiguous) ----
    float inv[2];
    #pragma unroll
    for (int hf = 0; hf < 2; hf++) {
        float ls = lrow[hf];
        ls += __shfl_xor_sync(0xffffffffu, ls, 1);
        ls += __shfl_xor_sync(0xffffffffu, ls, 2);
        inv[hf] = 1.0f / ls;
    }
    #pragma unroll
    for (int hf = 0; hf < 2; hf++) {
        int srow = qt * 128 + warp * 16 + lr + hf * 8;
        size_t base = ((size_t)(b * 16 + h) * 2048 + srow) << 7;
        #pragma unroll
        for (int ni = 0; ni < 16; ni++) {
            int d = ni * 8 + lc * 2;
            uint32_t hh;
            PACKH(hh, accO[ni][hf * 2 + 1] * inv[hf], accO[ni][hf * 2] * inv[hf]);
            *(uint32_t*)(o + base + d) = hh;
        }
    }
}

// ---------------------------------------------------------------------------
extern "C" void kernel_launch(void* const* d_in, const int* in_sizes, int n_in,
                              void* d_out, int out_size)
{
    (void)in_sizes; (void)n_in; (void)out_size;
    const float* x    = (const float*)d_in[0];
    const float* wqkv = (const float*)d_in[1];
    const float* wout = (const float*)d_in[2];
    float* out = (float*)d_out;

    __half *qkv, *xF, *wqF, *woF, *oF;
    cudaGetSymbolAddress((void**)&qkv, g_qkv);
    cudaGetSymbolAddress((void**)&xF, g_xF);
    cudaGetSymbolAddress((void**)&wqF, g_wqF);
    cudaGetSymbolAddress((void**)&woF, g_woF);
    cudaGetSymbolAddress((void**)&oF, g_oF);

    cudaFuncSetAttribute(gemm_fp16,
                         cudaFuncAttributeMaxDynamicSharedMemorySize, GSMEM);
    cudaFuncSetAttribute(flash_fp16,
                         cudaFuncAttributeMaxDynamicSharedMemorySize, FSMEM);

    khalf<<<(M_TOT * GK / 4 + 255) / 256, 256>>>(x, xF, M_TOT * GK / 4);
    khalfT<<<dim3(NQKV / 32, GK / 32), dim3(32, 8)>>>(wqkv, wqF, GK, NQKV);
    khalfT<<<dim3(GK / 32, GK / 32), dim3(32, 8)>>>(wout, woF, GK, GK);

    // 1) QKV projection -> fp16 (Q pre-scaled)
    gemm_fp16<<<dim3(NQKV / 128, M_TOT / 128), 256, GSMEM>>>(
        xF, wqF, nullptr, qkv, NQKV, 1);

    // 2) causal attention (all fp16) -> fp16 O
    flash_fp16<<<dim3(16, 16, 4), 256, FSMEM>>>(qkv, oF);

    // 3) output projection -> fp32 out
    gemm_fp16<<<dim3(GK / 128, M_TOT / 128), 256, GSMEM>>>(
        oF, woF, out, nullptr, GK, 0);
}

// round 14
// speedup vs baseline: 2.7936x; 1.0725x over previous
#include <cuda_runtime.h>
#include <cuda_bf16.h>
#include <cuda_fp16.h>
#include <cstdint>
#include <math.h>

#define M_TOT 8192
#define NQKV  6144
#define GK    2048

// ---------------- device scratch (all fp16 single precision) ----------------
__device__ __half g_qkv[(size_t)M_TOT * NQKV];   // Q (pre-scaled) | K | V
__device__ __half g_xF[(size_t)M_TOT * GK];
__device__ __half g_wqF[(size_t)NQKV * GK];      // W_qkv^T
__device__ __half g_woF[(size_t)GK * GK];        // W_out^T
__device__ __half g_oF[(size_t)M_TOT * GK];      // attention out

#define QSCALE (0.08838834764831845f * 1.4426950408889634f)

// ---------------- helpers ----------------
#define CPA16(dst, src) \
    asm volatile("cp.async.cg.shared.global [%0], [%1], 16;" :: "r"(dst), "l"(src))
#define CPA_COMMIT() asm volatile("cp.async.commit_group;")
#define CPA_WAIT2()  asm volatile("cp.async.wait_group 2;")
#define CPA_WAIT1()  asm volatile("cp.async.wait_group 1;")
#define CPA_WAIT0()  asm volatile("cp.async.wait_group 0;")

#define MMAH16816(ac, a0, a1, a2, a3, b0, b1) \
    asm volatile("mma.sync.aligned.m16n8k16.row.col.f32.f16.f16.f32 " \
        "{%0,%1,%2,%3},{%4,%5,%6,%7},{%8,%9},{%0,%1,%2,%3};" \
        : "+f"((ac)[0]), "+f"((ac)[1]), "+f"((ac)[2]), "+f"((ac)[3]) \
        : "r"(a0), "r"(a1), "r"(a2), "r"(a3), "r"(b0), "r"(b1))

#define LDSM4(r0, r1, r2, r3, addr) \
    asm volatile("ldmatrix.sync.aligned.m8n8.x4.shared.b16 {%0,%1,%2,%3}, [%4];" \
        : "=r"(r0), "=r"(r1), "=r"(r2), "=r"(r3) : "r"(addr))
#define LDSM4T(r0, r1, r2, r3, addr) \
    asm volatile("ldmatrix.sync.aligned.m8n8.x4.trans.shared.b16 {%0,%1,%2,%3}, [%4];" \
        : "=r"(r0), "=r"(r1), "=r"(r2), "=r"(r3) : "r"(addr))

// pack two fp32 -> fp16x2 (x1 -> hi half, x0 -> lo half)
#define PACKH(d, x1, x0) \
    asm("cvt.rn.f16x2.f32 %0, %1, %2;" : "=r"(d) : "f"(x1), "f"(x0))

// pack then exp2 both halves in one MUFU op
#define EXP2PAIR(d, x1, x0) do {                                     \
    uint32_t _t;                                                     \
    asm("cvt.rn.f16x2.f32 %0, %1, %2;" : "=r"(_t) : "f"(x1), "f"(x0)); \
    asm("ex2.approx.f16x2 %0, %1;" : "=r"(d) : "r"(_t));             \
} while (0)

// ---------------- conversion kernels ----------------
__global__ void khalf(const float* __restrict__ in, __half* __restrict__ out, int n4)
{
    int i = blockIdx.x * blockDim.x + threadIdx.x;
    if (i >= n4) return;
    float4 v = ((const float4*)in)[i];
    uint2 o;
    PACKH(o.x, v.y, v.x);
    PACKH(o.y, v.w, v.z);
    ((uint2*)out)[i] = o;
}

// in [K, N] row-major -> out^T [N, K] fp16
__global__ void khalfT(const float* __restrict__ in, __half* __restrict__ outT, int K, int N)
{
    __shared__ float t[32][33];
    int n0 = blockIdx.x * 32, k0 = blockIdx.y * 32;
    int tx = threadIdx.x, ty = threadIdx.y;
    #pragma unroll
    for (int j = 0; j < 32; j += 8)
        t[ty + j][tx] = in[(size_t)(k0 + ty + j) * N + n0 + tx];
    __syncthreads();
    #pragma unroll
    for (int j = 0; j < 32; j += 8)
        outT[(size_t)(n0 + ty + j) * K + k0 + tx] = __float2half(t[tx][ty + j]);
}

// ---------------- fp16 single-pass GEMM ----------------
// C[M,N] = A[M,K] @ B[Ntot,K]^T. Block 128x128xK64 chunks, 8 warps 64x32,
// 3-stage cp.async pipeline. 32 sync boundaries (vs 64 at k32).
#define SROW    144                 // 64 halfs = 128B data + 16B pad
#define TILE_B  (128 * SROW)        // 18432
#define STAGE_B (2 * TILE_B)        // 36864: A | B
#define GSMEM   (3 * STAGE_B)       // 110592

__global__ __launch_bounds__(256, 2)
void gemm_fp16(const __half* __restrict__ A, const __half* __restrict__ B,
               float* __restrict__ C, __half* __restrict__ Ch,
               int ldc, int mode)
{
    extern __shared__ __align__(16) char smem[];
    const uint32_t sbase = (uint32_t)__cvta_generic_to_shared(smem);
    const int tid  = threadIdx.x;
    const int warp = tid >> 5, lane = tid & 31;
    const int m0 = blockIdx.y * 128, n0 = blockIdx.x * 128;
    const int wm = (warp & 1) * 64, wn = (warp >> 1) * 32;

    auto issue = [&](int st, int k0) {
        uint32_t dbase = sbase + st * STAGE_B;
        #pragma unroll
        for (int t = 0; t < 8; t++) {
            int i = tid + t * 256;
            int sub = i >> 10;               // 0 = A, 1 = B
            int j = i & 1023;
            int r = j >> 3, c = j & 7;       // 128 rows x 8 16B-chunks
            const __half* g = (sub == 0)
                ? A + (size_t)(m0 + r) * GK + k0 + c * 8
                : B + (size_t)(n0 + r) * GK + k0 + c * 8;
            CPA16(dbase + sub * TILE_B + r * SROW + c * 16, (const void*)g);
        }
        CPA_COMMIT();
    };

    float acc[4][4][4];
    #pragma unroll
    for (int mi = 0; mi < 4; mi++)
        #pragma unroll
        for (int ni = 0; ni < 4; ni++)
            #pragma unroll
            for (int q = 0; q < 4; q++) acc[mi][ni][q] = 0.0f;

    issue(0, 0);
    issue(1, 64);

    const int lr = lane >> 2;
    const int arow = lane & 15, ahalf = (lane >> 4) * 16;
    const int brow = (lane & 7) + ((lane >> 4) << 3);
    const int bhalf = ((lane >> 3) & 1) * 16;

    for (int ch = 0; ch < 32; ch++) {
        int buf = ch % 3;
        if (ch + 2 < 32)      { issue((ch + 2) % 3, (ch + 2) * 64); CPA_WAIT2(); }
        else if (ch + 1 < 32) { CPA_WAIT1(); }
        else                  { CPA_WAIT0(); }
        __syncthreads();

        const uint32_t sA = sbase + buf * STAGE_B;
        const uint32_t sB = sA + TILE_B;

        #pragma unroll
        for (int k16 = 0; k16 < 4; k16++) {
            const int kb2 = k16 * 32;
            uint32_t bh[4][2];
            #pragma unroll
            for (int np = 0; np < 2; np++) {
                uint32_t ba = (wn + np * 16 + brow) * SROW + kb2 + bhalf;
                LDSM4(bh[2 * np][0], bh[2 * np][1], bh[2 * np + 1][0], bh[2 * np + 1][1],
                      sB + ba);
            }
            #pragma unroll
            for (int mi = 0; mi < 4; mi++) {
                uint32_t aa = (wm + mi * 16 + arow) * SROW + kb2 + ahalf;
                uint32_t a0, a1, a2, a3;
                LDSM4(a0, a1, a2, a3, sA + aa);
                #pragma unroll
                for (int ni = 0; ni < 4; ni++)
                    MMAH16816(acc[mi][ni], a0, a1, a2, a3, bh[ni][0], bh[ni][1]);
            }
        }
        __syncthreads();
    }

    #pragma unroll
    for (int mi = 0; mi < 4; mi++) {
        int row = m0 + wm + mi * 16 + lr;
        #pragma unroll
        for (int ni = 0; ni < 4; ni++) {
            int col = n0 + wn + ni * 8 + (lane & 3) * 2;
            if (mode == 0) {
                float* p0 = C + (size_t)row * ldc + col;
                float* p1 = C + (size_t)(row + 8) * ldc + col;
                p0[0] = acc[mi][ni][0]; p0[1] = acc[mi][ni][1];
                p1[0] = acc[mi][ni][2]; p1[1] = acc[mi][ni][3];
            } else {
                float sc = (col < 2048) ? QSCALE : 1.0f;
                uint32_t d0, d1;
                PACKH(d0, acc[mi][ni][1] * sc, acc[mi][ni][0] * sc);
                PACKH(d1, acc[mi][ni][3] * sc, acc[mi][ni][2] * sc);
                *(uint32_t*)(Ch + (size_t)row * ldc + col) = d0;
                *(uint32_t*)(Ch + (size_t)(row + 8) * ldc + col) = d1;
            }
        }
    }
}

// ---------------- flash attention (fp16 single, mma.sync) ----------------
// Q,K,V,P all fp16; 1 S-pass + 1 PV-pass; exp via ex2.approx.f16x2.
#define SRA   272
#define TEN_B (128 * SRA)          // 34816
#define FSMEM (3 * TEN_B)          // 104448: Q | K(2x64) | V(2x64)

__global__ __launch_bounds__(256, 1)
void flash_fp16(const __half* __restrict__ qkv, __half* __restrict__ o)
{
    extern __shared__ __align__(16) char sm[];
    const uint32_t S0 = (uint32_t)__cvta_generic_to_shared(sm);
    const uint32_t oQ = 0, oK = TEN_B, oV = 2 * TEN_B;

    const int tid = threadIdx.x, warp = tid >> 5, lane = tid & 31;
    const int lr = lane >> 2, lc = lane & 3;
    const int qt = blockIdx.x, h = blockIdx.y, b = blockIdx.z;
    const size_t rowbase = (size_t)(b * 2048 + h * 128) * 6144;

    const int arow = lane & 15, ahalf = (lane >> 4) * 16;
    const int brow = (lane & 7) + ((lane >> 4) << 3);
    const int bhalf = ((lane >> 3) & 1) * 16;

    auto issue_kv = [&](int t64, int buf) {
        #pragma unroll
        for (int t = 0; t < 8; t++) {
            int i = tid + t * 256;
            int sub = i >> 10;                 // 0 K, 1 V
            int j = i & 1023;
            int r = j >> 4, c = j & 15;
            const __half* src = qkv + rowbase
                + (size_t)(t64 * 4 + (r >> 4)) * 6144 + ((r & 15) << 7)
                + (sub ? 4096 : 2048) + c * 8;
            uint32_t off = sub ? oV : oK;
            CPA16(S0 + off + (buf * 64 + r) * SRA + c * 16, src);
        }
        CPA_COMMIT();
    };

    // Q load (group 0): 128 rows x 16 chunks
    #pragma unroll
    for (int t = 0; t < 8; t++) {
        int i = tid + t * 256;
        int r = i >> 4, c = i & 15;
        const __half* src = qkv + rowbase
            + (size_t)(qt * 8 + (r >> 4)) * 6144 + ((r & 15) << 7) + c * 8;
        CPA16(S0 + oQ + r * SRA + c * 16, src);
    }
    CPA_COMMIT();

    const int nt = 2 * qt + 2;
    issue_kv(0, 0);

    float accO[16][4];
    #pragma unroll
    for (int ni = 0; ni < 16; ni++)
        #pragma unroll
        for (int q = 0; q < 4; q++) accO[ni][q] = 0.0f;
    float mrow[2] = {-1e30f, -1e30f}, lrow[2] = {0.0f, 0.0f};
    uint32_t qf[8][4];   // preloaded Q fragments

    for (int t64 = 0; t64 < nt; t64++) {
        int buf = t64 & 1;
        if (t64 + 1 < nt) { issue_kv(t64 + 1, buf ^ 1); CPA_WAIT1(); }
        else              { CPA_WAIT0(); }
        __syncthreads();

        if (t64 == 0) {
            #pragma unroll
            for (int dk = 0; dk < 8; dk++) {
                uint32_t qa = S0 + oQ + (warp * 16 + arow) * SRA + dk * 32 + ahalf;
                LDSM4(qf[dk][0], qf[dk][1], qf[dk][2], qf[dk][3], qa);
            }
        }

        const uint32_t kbB = buf * 64 * SRA;

        // ---- S = Q @ K^T (single fp16 pass) ----
        float sacc[8][4];
        #pragma unroll
        for (int ni = 0; ni < 8; ni++)
            #pragma unroll
            for (int q = 0; q < 4; q++) sacc[ni][q] = 0.0f;

        #pragma unroll
        for (int dk = 0; dk < 8; dk++) {
            #pragma unroll
            for (int np = 0; np < 4; np++) {
                uint32_t ka = S0 + oK + kbB + (np * 16 + brow) * SRA + dk * 32 + bhalf;
                uint32_t b0, b1, b2, b3;
                LDSM4(b0, b1, b2, b3, ka);
                MMAH16816(sacc[2 * np], qf[dk][0], qf[dk][1], qf[dk][2], qf[dk][3], b0, b1);
                MMAH16816(sacc[2 * np + 1], qf[dk][0], qf[dk][1], qf[dk][2], qf[dk][3], b2, b3);
            }
        }

        // ---- causal mask ----
        if (t64 >= 2 * qt) {
            #pragma unroll
            for (int ni = 0; ni < 8; ni++)
                #pragma unroll
                for (int q = 0; q < 4; q++) {
                    int col_g = t64 * 64 + ni * 8 + lc * 2 + (q & 1);
                    int row_g = qt * 128 + warp * 16 + lr + (q >> 1) * 8;
                    if (col_g > row_g) sacc[ni][q] = -1e30f;
                }
        }

        // ---- online softmax; P packed fp16 via ex2.approx.f16x2 ----
        float corr[2];
        uint32_t ph[8][2];
        #pragma unroll
        for (int hf = 0; hf < 2; hf++) {
            float rm = -1e30f;
            #pragma unroll
            for (int ni = 0; ni < 8; ni++)
                rm = fmaxf(rm, fmaxf(sacc[ni][hf * 2], sacc[ni][hf * 2 + 1]));
            rm = fmaxf(rm, __shfl_xor_sync(0xffffffffu, rm, 1));
            rm = fmaxf(rm, __shfl_xor_sync(0xffffffffu, rm, 2));
            float mnew = fmaxf(mrow[hf], rm);
            corr[hf] = exp2f(mrow[hf] - mnew);
            mrow[hf] = mnew;
            float ls = 0.0f;
            #pragma unroll
            for (int ni = 0; ni < 8; ni++) {
                uint32_t p;
                EXP2PAIR(p, sacc[ni][hf * 2 + 1] - mnew, sacc[ni][hf * 2] - mnew);
                ph[ni][hf] = p;
                float2 f = __half22float2(*reinterpret_cast<__half2*>(&p));
                ls += f.x + f.y;
            }
            lrow[hf] = lrow[hf] * corr[hf] + ls;
        }
        #pragma unroll
        for (int ni = 0; ni < 16; ni++)
            #pragma unroll
            for (int q = 0; q < 4; q++) accO[ni][q] *= corr[q >> 1];

        // ---- O += P @ V (single fp16 pass) ----
        #pragma unroll
        for (int j = 0; j < 4; j++) {
            uint32_t pa0 = ph[2 * j][0], pa1 = ph[2 * j][1];
            uint32_t pa2 = ph[2 * j + 1][0], pa3 = ph[2 * j + 1][1];
            #pragma unroll
            for (int n2 = 0; n2 < 8; n2++) {
                uint32_t va = S0 + oV + kbB + (j * 16 + (lane & 15)) * SRA
                            + n2 * 32 + (lane >> 4) * 16;
                uint32_t v0, v1, v2, v3;
                LDSM4T(v0, v1, v2, v3, va);
                MMAH16816(accO[2 * n2], pa0, pa1, pa2, pa3, v0, v1);
                MMAH16816(accO[2 * n2 + 1], pa0, pa1, pa2, pa3, v2, v3);
            }
        }
        __syncthreads();
    }

    // ---- normalize + write O (fp16, head-contiguous) ----
    float inv[2];
    #pragma unroll
    for (int hf = 0; hf < 2; hf++) {
        float ls = lrow[hf];
        ls += __shfl_xor_sync(0xffffffffu, ls, 1);
        ls += __shfl_xor_sync(0xffffffffu, ls, 2);
        inv[hf] = 1.0f / ls;
    }
    #pragma unroll
    for (int hf = 0; hf < 2; hf++) {
        int srow = qt * 128 + warp * 16 + lr + hf * 8;
        size_t base = ((size_t)(b * 16 + h) * 2048 + srow) << 7;
        #pragma unroll
        for (int ni = 0; ni < 16; ni++) {
            int d = ni * 8 + lc * 2;
            uint32_t hh;
            PACKH(hh, accO[ni][hf * 2 + 1] * inv[hf], accO[ni][hf * 2] * inv[hf]);
            *(uint32_t*)(o + base + d) = hh;
        }
    }
}

// ---------------------------------------------------------------------------
extern "C" void kernel_launch(void* const* d_in, const int* in_sizes, int n_in,
                              void* d_out, int out_size)
{
    (void)in_sizes; (void)n_in; (void)out_size;
    const float* x    = (const float*)d_in[0];
    const float* wqkv = (const float*)d_in[1];
    const float* wout = (const float*)d_in[2];
    float* out = (float*)d_out;

    __half *qkv, *xF, *wqF, *woF, *oF;
    cudaGetSymbolAddress((void**)&qkv, g_qkv);
    cudaGetSymbolAddress((void**)&xF, g_xF);
    cudaGetSymbolAddress((void**)&wqF, g_wqF);
    cudaGetSymbolAddress((void**)&woF, g_woF);
    cudaGetSymbolAddress((void**)&oF, g_oF);

    cudaFuncSetAttribute(gemm_fp16,
                         cudaFuncAttributeMaxDynamicSharedMemorySize, GSMEM);
    cudaFuncSetAttribute(flash_fp16,
                         cudaFuncAttributeMaxDynamicSharedMemorySize, FSMEM);

    khalf<<<(M_TOT * GK / 4 + 255) / 256, 256>>>(x, xF, M_TOT * GK / 4);
    khalfT<<<dim3(NQKV / 32, GK / 32), dim3(32, 8)>>>(wqkv, wqF, GK, NQKV);
    khalfT<<<dim3(GK / 32, GK / 32), dim3(32, 8)>>>(wout, woF, GK, GK);

    // 1) QKV projection -> fp16 (Q pre-scaled)
    gemm_fp16<<<dim3(NQKV / 128, M_TOT / 128), 256, GSMEM>>>(
        xF, wqF, nullptr, qkv, NQKV, 1);

    // 2) causal attention (all fp16) -> fp16 O
    flash_fp16<<<dim3(16, 16, 4), 256, FSMEM>>>(qkv, oF);

    // 3) output projection -> fp32 out
    gemm_fp16<<<dim3(GK / 128, M_TOT / 128), 256, GSMEM>>>(
        oF, woF, out, nullptr, GK, 0);
}

// round 15
// speedup vs baseline: 2.7947x; 1.0004x over previous
#include <cuda_runtime.h>
#include <cuda_bf16.h>
#include <cuda_fp16.h>
#include <cstdint>
#include <math.h>

#define M_TOT 8192
#define NQKV  6144
#define GK    2048

// ---------------- device scratch (all fp16 single precision) ----------------
__device__ __half g_qkv[(size_t)M_TOT * NQKV];   // Q (pre-scaled) | K | V
__device__ __half g_xF[(size_t)M_TOT * GK];
__device__ __half g_wqF[(size_t)NQKV * GK];      // W_qkv^T
__device__ __half g_woF[(size_t)GK * GK];        // W_out^T
__device__ __half g_oF[(size_t)M_TOT * GK];      // attention out

#define QSCALE (0.08838834764831845f * 1.4426950408889634f)

// ---------------- helpers ----------------
#define CPA16(dst, src) \
    asm volatile("cp.async.cg.shared.global [%0], [%1], 16;" :: "r"(dst), "l"(src))
#define CPA_COMMIT() asm volatile("cp.async.commit_group;")
#define CPA_WAIT2()  asm volatile("cp.async.wait_group 2;")
#define CPA_WAIT1()  asm volatile("cp.async.wait_group 1;")
#define CPA_WAIT0()  asm volatile("cp.async.wait_group 0;")

#define MMAH16816(ac, a0, a1, a2, a3, b0, b1) \
    asm volatile("mma.sync.aligned.m16n8k16.row.col.f32.f16.f16.f32 " \
        "{%0,%1,%2,%3},{%4,%5,%6,%7},{%8,%9},{%0,%1,%2,%3};" \
        : "+f"((ac)[0]), "+f"((ac)[1]), "+f"((ac)[2]), "+f"((ac)[3]) \
        : "r"(a0), "r"(a1), "r"(a2), "r"(a3), "r"(b0), "r"(b1))

#define LDSM4(r0, r1, r2, r3, addr) \
    asm volatile("ldmatrix.sync.aligned.m8n8.x4.shared.b16 {%0,%1,%2,%3}, [%4];" \
        : "=r"(r0), "=r"(r1), "=r"(r2), "=r"(r3) : "r"(addr))
#define LDSM4T(r0, r1, r2, r3, addr) \
    asm volatile("ldmatrix.sync.aligned.m8n8.x4.trans.shared.b16 {%0,%1,%2,%3}, [%4];" \
        : "=r"(r0), "=r"(r1), "=r"(r2), "=r"(r3) : "r"(addr))

// pack two fp32 -> fp16x2 (x1 -> hi half, x0 -> lo half)
#define PACKH(d, x1, x0) \
    asm("cvt.rn.f16x2.f32 %0, %1, %2;" : "=r"(d) : "f"(x1), "f"(x0))

// pack then exp2 both halves in one MUFU op
#define EXP2PAIR(d, x1, x0) do {                                     \
    uint32_t _t;                                                     \
    asm("cvt.rn.f16x2.f32 %0, %1, %2;" : "=r"(_t) : "f"(x1), "f"(x0)); \
    asm("ex2.approx.f16x2 %0, %1;" : "=r"(d) : "r"(_t));             \
} while (0)

// ---------------- conversion kernels ----------------
__global__ void khalf(const float* __restrict__ in, __half* __restrict__ out, int n4)
{
    int i = blockIdx.x * blockDim.x + threadIdx.x;
    if (i >= n4) return;
    float4 v = ((const float4*)in)[i];
    uint2 o;
    PACKH(o.x, v.y, v.x);
    PACKH(o.y, v.w, v.z);
    ((uint2*)out)[i] = o;
}

// in [K, N] row-major -> out^T [N, K] fp16
__global__ void khalfT(const float* __restrict__ in, __half* __restrict__ outT, int K, int N)
{
    __shared__ float t[32][33];
    int n0 = blockIdx.x * 32, k0 = blockIdx.y * 32;
    int tx = threadIdx.x, ty = threadIdx.y;
    #pragma unroll
    for (int j = 0; j < 32; j += 8)
        t[ty + j][tx] = in[(size_t)(k0 + ty + j) * N + n0 + tx];
    __syncthreads();
    #pragma unroll
    for (int j = 0; j < 32; j += 8)
        outT[(size_t)(n0 + ty + j) * K + k0 + tx] = __float2half(t[tx][ty + j]);
}

// ---------------- fp16 single-pass GEMM ----------------
// C[M,N] = A[M,K] @ B[Ntot,K]^T. Block 128x128, 4 warps of 64x64 (crossbar diet:
// 8 LDSM.x4 per 32 MMAs = 128 B/MMA vs 192 before), k32 chunks, 3-stage cp.async,
// 3 CTAs/SM target.
#define SROW    80
#define TILE_B  (128 * SROW)        // 10240
#define STAGE_B (2 * TILE_B)        // 20480: A | B
#define GSMEM   (3 * STAGE_B)       // 61440

__global__ __launch_bounds__(128, 3)
void gemm_fp16(const __half* __restrict__ A, const __half* __restrict__ B,
               float* __restrict__ C, __half* __restrict__ Ch,
               int ldc, int mode)
{
    extern __shared__ __align__(16) char smem[];
    const uint32_t sbase = (uint32_t)__cvta_generic_to_shared(smem);
    const int tid  = threadIdx.x;
    const int warp = tid >> 5, lane = tid & 31;
    const int m0 = blockIdx.y * 128, n0 = blockIdx.x * 128;
    const int wm = (warp & 1) * 64, wn = (warp >> 1) * 64;

    auto issue = [&](int st, int k0) {
        uint32_t dbase = sbase + st * STAGE_B;
        #pragma unroll
        for (int t = 0; t < 8; t++) {
            int i = tid + t * 128;
            int sub = i >> 9;
            int j = i & 511;
            int r = j >> 2, c = j & 3;
            const __half* g = (sub == 0)
                ? A + (size_t)(m0 + r) * GK + k0 + c * 8
                : B + (size_t)(n0 + r) * GK + k0 + c * 8;
            CPA16(dbase + sub * TILE_B + r * SROW + c * 16, (const void*)g);
        }
        CPA_COMMIT();
    };

    float acc[4][8][4];
    #pragma unroll
    for (int mi = 0; mi < 4; mi++)
        #pragma unroll
        for (int ni = 0; ni < 8; ni++)
            #pragma unroll
            for (int q = 0; q < 4; q++) acc[mi][ni][q] = 0.0f;

    issue(0, 0);
    issue(1, 32);

    const int lr = lane >> 2;
    const int arow = lane & 15, ahalf = (lane >> 4) * 16;
    const int brow = (lane & 7) + ((lane >> 4) << 3);
    const int bhalf = ((lane >> 3) & 1) * 16;

    for (int ch = 0; ch < 64; ch++) {
        int buf = ch % 3;
        if (ch + 2 < 64)      { issue((ch + 2) % 3, (ch + 2) * 32); CPA_WAIT2(); }
        else if (ch + 1 < 64) { CPA_WAIT1(); }
        else                  { CPA_WAIT0(); }
        __syncthreads();

        const uint32_t sA = sbase + buf * STAGE_B;
        const uint32_t sB = sA + TILE_B;

        #pragma unroll
        for (int k16 = 0; k16 < 2; k16++) {
            const int kb2 = k16 * 32;
            uint32_t bh[8][2];
            #pragma unroll
            for (int np = 0; np < 4; np++) {
                uint32_t ba = (wn + np * 16 + brow) * SROW + kb2 + bhalf;
                LDSM4(bh[2 * np][0], bh[2 * np][1], bh[2 * np + 1][0], bh[2 * np + 1][1],
                      sB + ba);
            }
            #pragma unroll
            for (int mi = 0; mi < 4; mi++) {
                uint32_t aa = (wm + mi * 16 + arow) * SROW + kb2 + ahalf;
                uint32_t a0, a1, a2, a3;
                LDSM4(a0, a1, a2, a3, sA + aa);
                #pragma unroll
                for (int ni = 0; ni < 8; ni++)
                    MMAH16816(acc[mi][ni], a0, a1, a2, a3, bh[ni][0], bh[ni][1]);
            }
        }
        __syncthreads();
    }

    #pragma unroll
    for (int mi = 0; mi < 4; mi++) {
        int row = m0 + wm + mi * 16 + lr;
        #pragma unroll
        for (int ni = 0; ni < 8; ni++) {
            int col = n0 + wn + ni * 8 + (lane & 3) * 2;
            if (mode == 0) {
                float* p0 = C + (size_t)row * ldc + col;
                float* p1 = C + (size_t)(row + 8) * ldc + col;
                p0[0] = acc[mi][ni][0]; p0[1] = acc[mi][ni][1];
                p1[0] = acc[mi][ni][2]; p1[1] = acc[mi][ni][3];
            } else {
                float sc = (col < 2048) ? QSCALE : 1.0f;
                uint32_t d0, d1;
                PACKH(d0, acc[mi][ni][1] * sc, acc[mi][ni][0] * sc);
                PACKH(d1, acc[mi][ni][3] * sc, acc[mi][ni][2] * sc);
                *(uint32_t*)(Ch + (size_t)row * ldc + col) = d0;
                *(uint32_t*)(Ch + (size_t)(row + 8) * ldc + col) = d1;
            }
        }
    }
}

// ---------------- flash attention (fp16 single, mma.sync) ----------------
// Q,K,V,P all fp16; 1 S-pass + 1 PV-pass; exp via ex2.approx.f16x2.
#define SRA   272
#define TEN_B (128 * SRA)          // 34816
#define FSMEM (3 * TEN_B)          // 104448: Q | K(2x64) | V(2x64)

__global__ __launch_bounds__(256, 1)
void flash_fp16(const __half* __restrict__ qkv, __half* __restrict__ o)
{
    extern __shared__ __align__(16) char sm[];
    const uint32_t S0 = (uint32_t)__cvta_generic_to_shared(sm);
    const uint32_t oQ = 0, oK = TEN_B, oV = 2 * TEN_B;

    const int tid = threadIdx.x, warp = tid >> 5, lane = tid & 31;
    const int lr = lane >> 2, lc = lane & 3;
    const int qt = blockIdx.x, h = blockIdx.y, b = blockIdx.z;
    const size_t rowbase = (size_t)(b * 2048 + h * 128) * 6144;

    const int arow = lane & 15, ahalf = (lane >> 4) * 16;
    const int brow = (lane & 7) + ((lane >> 4) << 3);
    const int bhalf = ((lane >> 3) & 1) * 16;

    auto issue_kv = [&](int t64, int buf) {
        #pragma unroll
        for (int t = 0; t < 8; t++) {
            int i = tid + t * 256;
            int sub = i >> 10;                 // 0 K, 1 V
            int j = i & 1023;
            int r = j >> 4, c = j & 15;
            const __half* src = qkv + rowbase
                + (size_t)(t64 * 4 + (r >> 4)) * 6144 + ((r & 15) << 7)
                + (sub ? 4096 : 2048) + c * 8;
            uint32_t off = sub ? oV : oK;
            CPA16(S0 + off + (buf * 64 + r) * SRA + c * 16, src);
        }
        CPA_COMMIT();
    };

    // Q load (group 0): 128 rows x 16 chunks
    #pragma unroll
    for (int t = 0; t < 8; t++) {
        int i = tid + t * 256;
        int r = i >> 4, c = i & 15;
        const __half* src = qkv + rowbase
            + (size_t)(qt * 8 + (r >> 4)) * 6144 + ((r & 15) << 7) + c * 8;
        CPA16(S0 + oQ + r * SRA + c * 16, src);
    }
    CPA_COMMIT();

    const int nt = 2 * qt + 2;
    issue_kv(0, 0);

    float accO[16][4];
    #pragma unroll
    for (int ni = 0; ni < 16; ni++)
        #pragma unroll
        for (int q = 0; q < 4; q++) accO[ni][q] = 0.0f;
    float mrow[2] = {-1e30f, -1e30f}, lrow[2] = {0.0f, 0.0f};
    uint32_t qf[8][4];   // preloaded Q fragments

    for (int t64 = 0; t64 < nt; t64++) {
        int buf = t64 & 1;
        if (t64 + 1 < nt) { issue_kv(t64 + 1, buf ^ 1); CPA_WAIT1(); }
        else              { CPA_WAIT0(); }
        __syncthreads();

        if (t64 == 0) {
            #pragma unroll
            for (int dk = 0; dk < 8; dk++) {
                uint32_t qa = S0 + oQ + (warp * 16 + arow) * SRA + dk * 32 + ahalf;
                LDSM4(qf[dk][0], qf[dk][1], qf[dk][2], qf[dk][3], qa);
            }
        }

        const uint32_t kbB = buf * 64 * SRA;

        // ---- S = Q @ K^T (single fp16 pass) ----
        float sacc[8][4];
        #pragma unroll
        for (int ni = 0; ni < 8; ni++)
            #pragma unroll
            for (int q = 0; q < 4; q++) sacc[ni][q] = 0.0f;

        #pragma unroll
        for (int dk = 0; dk < 8; dk++) {
            #pragma unroll
            for (int np = 0; np < 4; np++) {
                uint32_t ka = S0 + oK + kbB + (np * 16 + brow) * SRA + dk * 32 + bhalf;
                uint32_t b0, b1, b2, b3;
                LDSM4(b0, b1, b2, b3, ka);
                MMAH16816(sacc[2 * np], qf[dk][0], qf[dk][1], qf[dk][2], qf[dk][3], b0, b1);
                MMAH16816(sacc[2 * np + 1], qf[dk][0], qf[dk][1], qf[dk][2], qf[dk][3], b2, b3);
            }
        }

        // ---- causal mask ----
        if (t64 >= 2 * qt) {
            #pragma unroll
            for (int ni = 0; ni < 8; ni++)
                #pragma unroll
                for (int q = 0; q < 4; q++) {
                    int col_g = t64 * 64 + ni * 8 + lc * 2 + (q & 1);
                    int row_g = qt * 128 + warp * 16 + lr + (q >> 1) * 8;
                    if (col_g > row_g) sacc[ni][q] = -1e30f;
                }
        }

        // ---- online softmax; P packed fp16 via ex2.approx.f16x2 ----
        float corr[2];
        uint32_t ph[8][2];
        #pragma unroll
        for (int hf = 0; hf < 2; hf++) {
            float rm = -1e30f;
            #pragma unroll
            for (int ni = 0; ni < 8; ni++)
                rm = fmaxf(rm, fmaxf(sacc[ni][hf * 2], sacc[ni][hf * 2 + 1]));
            rm = fmaxf(rm, __shfl_xor_sync(0xffffffffu, rm, 1));
            rm = fmaxf(rm, __shfl_xor_sync(0xffffffffu, rm, 2));
            float mnew = fmaxf(mrow[hf], rm);
            corr[hf] = exp2f(mrow[hf] - mnew);
            mrow[hf] = mnew;
            float ls = 0.0f;
            #pragma unroll
            for (int ni = 0; ni < 8; ni++) {
                uint32_t p;
                EXP2PAIR(p, sacc[ni][hf * 2 + 1] - mnew, sacc[ni][hf * 2] - mnew);
                ph[ni][hf] = p;
                float2 f = __half22float2(*reinterpret_cast<__half2*>(&p));
                ls += f.x + f.y;
            }
            lrow[hf] = lrow[hf] * corr[hf] + ls;
        }
        #pragma unroll
        for (int ni = 0; ni < 16; ni++)
            #pragma unroll
            for (int q = 0; q < 4; q++) accO[ni][q] *= corr[q >> 1];

        // ---- O += P @ V (single fp16 pass) ----
        #pragma unroll
        for (int j = 0; j < 4; j++) {
            uint32_t pa0 = ph[2 * j][0], pa1 = ph[2 * j][1];
            uint32_t pa2 = ph[2 * j + 1][0], pa3 = ph[2 * j + 1][1];
            #pragma unroll
            for (int n2 = 0; n2 < 8; n2++) {
                uint32_t va = S0 + oV + kbB + (j * 16 + (lane & 15)) * SRA
                            + n2 * 32 + (lane >> 4) * 16;
                uint32_t v0, v1, v2, v3;
                LDSM4T(v0, v1, v2, v3, va);
                MMAH16816(accO[2 * n2], pa0, pa1, pa2, pa3, v0, v1);
                MMAH16816(accO[2 * n2 + 1], pa0, pa1, pa2, pa3, v2, v3);
            }
        }
        __syncthreads();
    }

    // ---- normalize + write O (fp16, head-contiguous) ----
    float inv[2];
    #pragma unroll
    for (int hf = 0; hf < 2; hf++) {
        float ls = lrow[hf];
        ls += __shfl_xor_sync(0xffffffffu, ls, 1);
        ls += __shfl_xor_sync(0xffffffffu, ls, 2);
        inv[hf] = 1.0f / ls;
    }
    #pragma unroll
    for (int hf = 0; hf < 2; hf++) {
        int srow = qt * 128 + warp * 16 + lr + hf * 8;
        size_t base = ((size_t)(b * 16 + h) * 2048 + srow) << 7;
        #pragma unroll
        for (int ni = 0; ni < 16; ni++) {
            int d = ni * 8 + lc * 2;
            uint32_t hh;
            PACKH(hh, accO[ni][hf * 2 + 1] * inv[hf], accO[ni][hf * 2] * inv[hf]);
            *(uint32_t*)(o + base + d) = hh;
        }
    }
}

// ---------------------------------------------------------------------------
extern "C" void kernel_launch(void* const* d_in, const int* in_sizes, int n_in,
                              void* d_out, int out_size)
{
    (void)in_sizes; (void)n_in; (void)out_size;
    const float* x    = (const float*)d_in[0];
    const float* wqkv = (const float*)d_in[1];
    const float* wout = (const float*)d_in[2];
    float* out = (float*)d_out;

    __half *qkv, *xF, *wqF, *woF, *oF;
    cudaGetSymbolAddress((void**)&qkv, g_qkv);
    cudaGetSymbolAddress((void**)&xF, g_xF);
    cudaGetSymbolAddress((void**)&wqF, g_wqF);
    cudaGetSymbolAddress((void**)&woF, g_woF);
    cudaGetSymbolAddress((void**)&oF, g_oF);

    cudaFuncSetAttribute(gemm_fp16,
                         cudaFuncAttributeMaxDynamicSharedMemorySize, GSMEM);
    cudaFuncSetAttribute(flash_fp16,
                         cudaFuncAttributeMaxDynamicSharedMemorySize, FSMEM);

    khalf<<<(M_TOT * GK / 4 + 255) / 256, 256>>>(x, xF, M_TOT * GK / 4);
    khalfT<<<dim3(NQKV / 32, GK / 32), dim3(32, 8)>>>(wqkv, wqF, GK, NQKV);
    khalfT<<<dim3(GK / 32, GK / 32), dim3(32, 8)>>>(wout, woF, GK, GK);

    // 1) QKV projection -> fp16 (Q pre-scaled)
    gemm_fp16<<<dim3(NQKV / 128, M_TOT / 128), 128, GSMEM>>>(
        xF, wqF, nullptr, qkv, NQKV, 1);

    // 2) causal attention (all fp16) -> fp16 O
    flash_fp16<<<dim3(16, 16, 4), 256, FSMEM>>>(qkv, oF);

    // 3) output projection -> fp32 out
    gemm_fp16<<<dim3(GK / 128, M_TOT / 128), 128, GSMEM>>>(
        oF, woF, out, nullptr, GK, 0);
}

// round 16
// speedup vs baseline: 2.8346x; 1.0143x over previous
#include <cuda_runtime.h>
#include <cuda_bf16.h>
#include <cuda_fp16.h>
#include <cstdint>
#include <math.h>

#define M_TOT 8192
#define NQKV  6144
#define GK    2048

// ---------------- device scratch (all fp16 single precision) ----------------
__device__ __half g_qkv[(size_t)M_TOT * NQKV];   // Q (pre-scaled) | K | V
__device__ __half g_xF[(size_t)M_TOT * GK];
__device__ __half g_wqF[(size_t)NQKV * GK];      // W_qkv^T
__device__ __half g_woF[(size_t)GK * GK];        // W_out^T
__device__ __half g_oF[(size_t)M_TOT * GK];      // attention out

#define QSCALE (0.08838834764831845f * 1.4426950408889634f)

// ---------------- helpers ----------------
#define CPA16(dst, src) \
    asm volatile("cp.async.cg.shared.global [%0], [%1], 16;" :: "r"(dst), "l"(src))
#define CPA_COMMIT() asm volatile("cp.async.commit_group;")
#define CPA_WAIT1()  asm volatile("cp.async.wait_group 1;")
#define CPA_WAIT0()  asm volatile("cp.async.wait_group 0;")

#define MMAH16816(ac, a0, a1, a2, a3, b0, b1) \
    asm volatile("mma.sync.aligned.m16n8k16.row.col.f32.f16.f16.f32 " \
        "{%0,%1,%2,%3},{%4,%5,%6,%7},{%8,%9},{%0,%1,%2,%3};" \
        : "+f"((ac)[0]), "+f"((ac)[1]), "+f"((ac)[2]), "+f"((ac)[3]) \
        : "r"(a0), "r"(a1), "r"(a2), "r"(a3), "r"(b0), "r"(b1))

#define LDSM4(r0, r1, r2, r3, addr) \
    asm volatile("ldmatrix.sync.aligned.m8n8.x4.shared.b16 {%0,%1,%2,%3}, [%4];" \
        : "=r"(r0), "=r"(r1), "=r"(r2), "=r"(r3) : "r"(addr))
#define LDSM4T(r0, r1, r2, r3, addr) \
    asm volatile("ldmatrix.sync.aligned.m8n8.x4.trans.shared.b16 {%0,%1,%2,%3}, [%4];" \
        : "=r"(r0), "=r"(r1), "=r"(r2), "=r"(r3) : "r"(addr))

// pack two fp32 -> fp16x2 (x1 -> hi half, x0 -> lo half)
#define PACKH(d, x1, x0) \
    asm("cvt.rn.f16x2.f32 %0, %1, %2;" : "=r"(d) : "f"(x1), "f"(x0))

// pack then exp2 both halves in one MUFU op
#define EXP2PAIR(d, x1, x0) do {                                     \
    uint32_t _t;                                                     \
    asm("cvt.rn.f16x2.f32 %0, %1, %2;" : "=r"(_t) : "f"(x1), "f"(x0)); \
    asm("ex2.approx.f16x2 %0, %1;" : "=r"(d) : "r"(_t));             \
} while (0)

// ---------------- conversion kernels ----------------
__global__ void khalf(const float* __restrict__ in, __half* __restrict__ out, int n4)
{
    int i = blockIdx.x * blockDim.x + threadIdx.x;
    if (i >= n4) return;
    float4 v = ((const float4*)in)[i];
    uint2 o;
    PACKH(o.x, v.y, v.x);
    PACKH(o.y, v.w, v.z);
    ((uint2*)out)[i] = o;
}

// in [K, N] row-major -> out^T [N, K] fp16
__global__ void khalfT(const float* __restrict__ in, __half* __restrict__ outT, int K, int N)
{
    __shared__ float t[32][33];
    int n0 = blockIdx.x * 32, k0 = blockIdx.y * 32;
    int tx = threadIdx.x, ty = threadIdx.y;
    #pragma unroll
    for (int j = 0; j < 32; j += 8)
        t[ty + j][tx] = in[(size_t)(k0 + ty + j) * N + n0 + tx];
    __syncthreads();
    #pragma unroll
    for (int j = 0; j < 32; j += 8)
        outT[(size_t)(n0 + ty + j) * K + k0 + tx] = __float2half(t[tx][ty + j]);
}

// ---------------- fp16 single-pass GEMM ----------------
// C[M,N] = A[M,K] @ B[Ntot,K]^T. Block 128x128, 4 warps of 64x64,
// k32 chunks, 3-stage cp.async, SINGLE barrier per chunk
// (wait -> sync -> issue(ch+2) -> compute; issue targets the buffer whose
//  readers finished before this barrier).
#define SROW    80
#define TILE_B  (128 * SROW)        // 10240
#define STAGE_B (2 * TILE_B)        // 20480: A | B
#define GSMEM   (3 * STAGE_B)       // 61440

__global__ __launch_bounds__(128, 3)
void gemm_fp16(const __half* __restrict__ A, const __half* __restrict__ B,
               float* __restrict__ C, __half* __restrict__ Ch,
               int ldc, int mode)
{
    extern __shared__ __align__(16) char smem[];
    const uint32_t sbase = (uint32_t)__cvta_generic_to_shared(smem);
    const int tid  = threadIdx.x;
    const int warp = tid >> 5, lane = tid & 31;
    const int m0 = blockIdx.y * 128, n0 = blockIdx.x * 128;
    const int wm = (warp & 1) * 64, wn = (warp >> 1) * 64;

    auto issue = [&](int st, int k0) {
        uint32_t dbase = sbase + st * STAGE_B;
        #pragma unroll
        for (int t = 0; t < 8; t++) {
            int i = tid + t * 128;
            int sub = i >> 9;
            int j = i & 511;
            int r = j >> 2, c = j & 3;
            const __half* g = (sub == 0)
                ? A + (size_t)(m0 + r) * GK + k0 + c * 8
                : B + (size_t)(n0 + r) * GK + k0 + c * 8;
            CPA16(dbase + sub * TILE_B + r * SROW + c * 16, (const void*)g);
        }
        CPA_COMMIT();
    };

    float acc[4][8][4];
    #pragma unroll
    for (int mi = 0; mi < 4; mi++)
        #pragma unroll
        for (int ni = 0; ni < 8; ni++)
            #pragma unroll
            for (int q = 0; q < 4; q++) acc[mi][ni][q] = 0.0f;

    issue(0, 0);
    issue(1, 32);

    const int lr = lane >> 2;
    const int arow = lane & 15, ahalf = (lane >> 4) * 16;
    const int brow = (lane & 7) + ((lane >> 4) << 3);
    const int bhalf = ((lane >> 3) & 1) * 16;

    for (int ch = 0; ch < 64; ch++) {
        int buf = ch % 3;
        if (ch < 63) { CPA_WAIT1(); }   // newest group is issued AFTER this wait
        else         { CPA_WAIT0(); }
        __syncthreads();                // all readers of buffer (ch-1)%3 done

        if (ch + 2 < 64) issue((ch + 2) % 3, (ch + 2) * 32);

        const uint32_t sA = sbase + buf * STAGE_B;
        const uint32_t sB = sA + TILE_B;

        #pragma unroll
        for (int k16 = 0; k16 < 2; k16++) {
            const int kb2 = k16 * 32;
            uint32_t bh[8][2];
            #pragma unroll
            for (int np = 0; np < 4; np++) {
                uint32_t ba = (wn + np * 16 + brow) * SROW + kb2 + bhalf;
                LDSM4(bh[2 * np][0], bh[2 * np][1], bh[2 * np + 1][0], bh[2 * np + 1][1],
                      sB + ba);
            }
            #pragma unroll
            for (int mi = 0; mi < 4; mi++) {
                uint32_t aa = (wm + mi * 16 + arow) * SROW + kb2 + ahalf;
                uint32_t a0, a1, a2, a3;
                LDSM4(a0, a1, a2, a3, sA + aa);
                #pragma unroll
                for (int ni = 0; ni < 8; ni++)
                    MMAH16816(acc[mi][ni], a0, a1, a2, a3, bh[ni][0], bh[ni][1]);
            }
        }
    }

    #pragma unroll
    for (int mi = 0; mi < 4; mi++) {
        int row = m0 + wm + mi * 16 + lr;
        #pragma unroll
        for (int ni = 0; ni < 8; ni++) {
            int col = n0 + wn + ni * 8 + (lane & 3) * 2;
            if (mode == 0) {
                float* p0 = C + (size_t)row * ldc + col;
                float* p1 = C + (size_t)(row + 8) * ldc + col;
                p0[0] = acc[mi][ni][0]; p0[1] = acc[mi][ni][1];
                p1[0] = acc[mi][ni][2]; p1[1] = acc[mi][ni][3];
            } else {
                float sc = (col < 2048) ? QSCALE : 1.0f;
                uint32_t d0, d1;
                PACKH(d0, acc[mi][ni][1] * sc, acc[mi][ni][0] * sc);
                PACKH(d1, acc[mi][ni][3] * sc, acc[mi][ni][2] * sc);
                *(uint32_t*)(Ch + (size_t)row * ldc + col) = d0;
                *(uint32_t*)(Ch + (size_t)(row + 8) * ldc + col) = d1;
            }
        }
    }
}

// ---------------- flash attention (fp16 single, mma.sync) ----------------
// Q,K,V,P all fp16; 1 S-pass + 1 PV-pass; exp via ex2.approx.f16x2.
// Single barrier per tile: wait0 -> sync -> issue(t+1) -> compute.
#define SRA   272
#define TEN_B (128 * SRA)          // 34816
#define FSMEM (3 * TEN_B)          // 104448: Q | K(2x64) | V(2x64)

__global__ __launch_bounds__(256, 1)
void flash_fp16(const __half* __restrict__ qkv, __half* __restrict__ o)
{
    extern __shared__ __align__(16) char sm[];
    const uint32_t S0 = (uint32_t)__cvta_generic_to_shared(sm);
    const uint32_t oQ = 0, oK = TEN_B, oV = 2 * TEN_B;

    const int tid = threadIdx.x, warp = tid >> 5, lane = tid & 31;
    const int lr = lane >> 2, lc = lane & 3;
    const int qt = blockIdx.x, h = blockIdx.y, b = blockIdx.z;
    const size_t rowbase = (size_t)(b * 2048 + h * 128) * 6144;

    const int arow = lane & 15, ahalf = (lane >> 4) * 16;
    const int brow = (lane & 7) + ((lane >> 4) << 3);
    const int bhalf = ((lane >> 3) & 1) * 16;

    auto issue_kv = [&](int t64, int buf) {
        #pragma unroll
        for (int t = 0; t < 8; t++) {
            int i = tid + t * 256;
            int sub = i >> 10;                 // 0 K, 1 V
            int j = i & 1023;
            int r = j >> 4, c = j & 15;
            const __half* src = qkv + rowbase
                + (size_t)(t64 * 4 + (r >> 4)) * 6144 + ((r & 15) << 7)
                + (sub ? 4096 : 2048) + c * 8;
            uint32_t off = sub ? oV : oK;
            CPA16(S0 + off + (buf * 64 + r) * SRA + c * 16, src);
        }
        CPA_COMMIT();
    };

    // Q load (group 0): 128 rows x 16 chunks
    #pragma unroll
    for (int t = 0; t < 8; t++) {
        int i = tid + t * 256;
        int r = i >> 4, c = i & 15;
        const __half* src = qkv + rowbase
            + (size_t)(qt * 8 + (r >> 4)) * 6144 + ((r & 15) << 7) + c * 8;
        CPA16(S0 + oQ + r * SRA + c * 16, src);
    }
    CPA_COMMIT();

    const int nt = 2 * qt + 2;
    issue_kv(0, 0);

    float accO[16][4];
    #pragma unroll
    for (int ni = 0; ni < 16; ni++)
        #pragma unroll
        for (int q = 0; q < 4; q++) accO[ni][q] = 0.0f;
    float mrow[2] = {-1e30f, -1e30f}, lrow[2] = {0.0f, 0.0f};
    uint32_t qf[8][4];   // preloaded Q fragments

    for (int t64 = 0; t64 < nt; t64++) {
        int buf = t64 & 1;
        CPA_WAIT0();          // kv(t64) [and Q on t64=0] fully landed
        __syncthreads();      // all readers of buffer buf^1 finished last iter

        if (t64 + 1 < nt) issue_kv(t64 + 1, buf ^ 1);

        if (t64 == 0) {
            #pragma unroll
            for (int dk = 0; dk < 8; dk++) {
                uint32_t qa = S0 + oQ + (warp * 16 + arow) * SRA + dk * 32 + ahalf;
                LDSM4(qf[dk][0], qf[dk][1], qf[dk][2], qf[dk][3], qa);
            }
        }

        const uint32_t kbB = buf * 64 * SRA;

        // ---- S = Q @ K^T (single fp16 pass) ----
        float sacc[8][4];
        #pragma unroll
        for (int ni = 0; ni < 8; ni++)
            #pragma unroll
            for (int q = 0; q < 4; q++) sacc[ni][q] = 0.0f;

        #pragma unroll
        for (int dk = 0; dk < 8; dk++) {
            #pragma unroll
            for (int np = 0; np < 4; np++) {
                uint32_t ka = S0 + oK + kbB + (np * 16 + brow) * SRA + dk * 32 + bhalf;
                uint32_t b0, b1, b2, b3;
                LDSM4(b0, b1, b2, b3, ka);
                MMAH16816(sacc[2 * np], qf[dk][0], qf[dk][1], qf[dk][2], qf[dk][3], b0, b1);
                MMAH16816(sacc[2 * np + 1], qf[dk][0], qf[dk][1], qf[dk][2], qf[dk][3], b2, b3);
            }
        }

        // ---- causal mask ----
        if (t64 >= 2 * qt) {
            #pragma unroll
            for (int ni = 0; ni < 8; ni++)
                #pragma unroll
                for (int q = 0; q < 4; q++) {
                    int col_g = t64 * 64 + ni * 8 + lc * 2 + (q & 1);
                    int row_g = qt * 128 + warp * 16 + lr + (q >> 1) * 8;
                    if (col_g > row_g) sacc[ni][q] = -1e30f;
                }
        }

        // ---- online softmax; P packed fp16 via ex2.approx.f16x2 ----
        float corr[2];
        uint32_t ph[8][2];
        #pragma unroll
        for (int hf = 0; hf < 2; hf++) {
            float rm = -1e30f;
            #pragma unroll
            for (int ni = 0; ni < 8; ni++)
                rm = fmaxf(rm, fmaxf(sacc[ni][hf * 2], sacc[ni][hf * 2 + 1]));
            rm = fmaxf(rm, __shfl_xor_sync(0xffffffffu, rm, 1));
            rm = fmaxf(rm, __shfl_xor_sync(0xffffffffu, rm, 2));
            float mnew = fmaxf(mrow[hf], rm);
            corr[hf] = exp2f(mrow[hf] - mnew);
            mrow[hf] = mnew;
            float ls = 0.0f;
            #pragma unroll
            for (int ni = 0; ni < 8; ni++) {
                uint32_t p;
                EXP2PAIR(p, sacc[ni][hf * 2 + 1] - mnew, sacc[ni][hf * 2] - mnew);
                ph[ni][hf] = p;
                float2 f = __half22float2(*reinterpret_cast<__half2*>(&p));
                ls += f.x + f.y;
            }
            lrow[hf] = lrow[hf] * corr[hf] + ls;
        }
        #pragma unroll
        for (int ni = 0; ni < 16; ni++)
            #pragma unroll
            for (int q = 0; q < 4; q++) accO[ni][q] *= corr[q >> 1];

        // ---- O += P @ V (single fp16 pass) ----
        #pragma unroll
        for (int j = 0; j < 4; j++) {
            uint32_t pa0 = ph[2 * j][0], pa1 = ph[2 * j][1];
            uint32_t pa2 = ph[2 * j + 1][0], pa3 = ph[2 * j + 1][1];
            #pragma unroll
            for (int n2 = 0; n2 < 8; n2++) {
                uint32_t va = S0 + oV + kbB + (j * 16 + (lane & 15)) * SRA
                            + n2 * 32 + (lane >> 4) * 16;
                uint32_t v0, v1, v2, v3;
                LDSM4T(v0, v1, v2, v3, va);
                MMAH16816(accO[2 * n2], pa0, pa1, pa2, pa3, v0, v1);
                MMAH16816(accO[2 * n2 + 1], pa0, pa1, pa2, pa3, v2, v3);
            }
        }
    }

    // ---- normalize + write O (fp16, head-contiguous) ----
    float inv[2];
    #pragma unroll
    for (int hf = 0; hf < 2; hf++) {
        float ls = lrow[hf];
        ls += __shfl_xor_sync(0xffffffffu, ls, 1);
        ls += __shfl_xor_sync(0xffffffffu, ls, 2);
        inv[hf] = 1.0f / ls;
    }
    #pragma unroll
    for (int hf = 0; hf < 2; hf++) {
        int srow = qt * 128 + warp * 16 + lr + hf * 8;
        size_t base = ((size_t)(b * 16 + h) * 2048 + srow) << 7;
        #pragma unroll
        for (int ni = 0; ni < 16; ni++) {
            int d = ni * 8 + lc * 2;
            uint32_t hh;
            PACKH(hh, accO[ni][hf * 2 + 1] * inv[hf], accO[ni][hf * 2] * inv[hf]);
            *(uint32_t*)(o + base + d) = hh;
        }
    }
}

// ---------------------------------------------------------------------------
extern "C" void kernel_launch(void* const* d_in, const int* in_sizes, int n_in,
                              void* d_out, int out_size)
{
    (void)in_sizes; (void)n_in; (void)out_size;
    const float* x    = (const float*)d_in[0];
    const float* wqkv = (const float*)d_in[1];
    const float* wout = (const float*)d_in[2];
    float* out = (float*)d_out;

    __half *qkv, *xF, *wqF, *woF, *oF;
    cudaGetSymbolAddress((void**)&qkv, g_qkv);
    cudaGetSymbolAddress((void**)&xF, g_xF);
    cudaGetSymbolAddress((void**)&wqF, g_wqF);
    cudaGetSymbolAddress((void**)&woF, g_woF);
    cudaGetSymbolAddress((void**)&oF, g_oF);

    cudaFuncSetAttribute(gemm_fp16,
                         cudaFuncAttributeMaxDynamicSharedMemorySize, GSMEM);
    cudaFuncSetAttribute(flash_fp16,
                         cudaFuncAttributeMaxDynamicSharedMemorySize, FSMEM);

    khalf<<<(M_TOT * GK / 4 + 255) / 256, 256>>>(x, xF, M_TOT * GK / 4);
    khalfT<<<dim3(NQKV / 32, GK / 32), dim3(32, 8)>>>(wqkv, wqF, GK, NQKV);
    khalfT<<<dim3(GK / 32, GK / 32), dim3(32, 8)>>>(wout, woF, GK, GK);

    // 1) QKV projection -> fp16 (Q pre-scaled)
    gemm_fp16<<<dim3(NQKV / 128, M_TOT / 128), 128, GSMEM>>>(
        xF, wqF, nullptr, qkv, NQKV, 1);

    // 2) causal attention (all fp16) -> fp16 O
    flash_fp16<<<dim3(16, 16, 4), 256, FSMEM>>>(qkv, oF);

    // 3) output projection -> fp32 out
    gemm_fp16<<<dim3(GK / 128, M_TOT / 128), 128, GSMEM>>>(
        oF, woF, out, nullptr, GK, 0);
}